// round 5
// baseline (speedup 1.0000x reference)
#include <cuda_runtime.h>
#include <cuda_bf16.h>

// ---------------------------------------------------------------------------
// AtlasAttention, legacy mma.sync bf16 split-3, fused MLP, ldmatrix fragments.
//   GEMM1: q = clip(hs@Wq) -> g_qs (fp32), split-3 HMMA
//   Fused per 128 flat rows: poly(q)->P smem; 8 chunks of 64 cols:
//       GEMM2 (P x W1chunk) -> relu+split -> H smem -> GEMM3 accum in regs
//   out = acc + b2.  Exact folds: b1eff (const poly block), W2[:, :64] slice.
//   All smem fragment loads via ldmatrix.m8n8.x4 (4x fewer LDS issue slots).
// ---------------------------------------------------------------------------

typedef unsigned int u32;

#define TOKENS 8192
#define HIDDEN 768
#define FLATR  98304
#define MEMH   512
#define KP     192
#define HD     64

__device__ __align__(16) __nv_bfloat16 g_hs_hi[TOKENS * HIDDEN];
__device__ __align__(16) __nv_bfloat16 g_hs_lo[TOKENS * HIDDEN];
__device__ __align__(16) __nv_bfloat16 g_wqt_hi[HIDDEN * HIDDEN];  // [n][k]
__device__ __align__(16) __nv_bfloat16 g_wqt_lo[HIDDEN * HIDDEN];
__device__ __align__(16) __nv_bfloat16 g_w1t_hi[MEMH * KP];        // [n=512][k=192]
__device__ __align__(16) __nv_bfloat16 g_w1t_lo[MEMH * KP];
__device__ __align__(16) __nv_bfloat16 g_w2t_hi[HD * MEMH];        // [n=64][k=512]
__device__ __align__(16) __nv_bfloat16 g_w2t_lo[HD * MEMH];
__device__ float g_qs[(size_t)FLATR * HD];                         // clipped q
__device__ float g_b1eff[MEMH];

// ---------------- helpers ----------------
__device__ __forceinline__ u32 smem_u32(const void* p) {
    u32 a; asm("{ .reg .u64 t; cvta.to.shared.u64 t, %1; cvt.u32.u64 %0, t; }"
               : "=r"(a) : "l"(p)); return a;
}
__device__ __forceinline__ u32 pack_bf(__nv_bfloat16 a, __nv_bfloat16 b) {
    return (u32)__bfloat16_as_ushort(a) | ((u32)__bfloat16_as_ushort(b) << 16);
}
__device__ __forceinline__ void split2(float v0, float v1, u32 &hi, u32 &lo) {
    __nv_bfloat16 h0 = __float2bfloat16(v0), h1 = __float2bfloat16(v1);
    __nv_bfloat16 l0 = __float2bfloat16(v0 - __bfloat162float(h0));
    __nv_bfloat16 l1 = __float2bfloat16(v1 - __bfloat162float(h1));
    hi = pack_bf(h0, h1); lo = pack_bf(l0, l1);
}
__device__ __forceinline__ void mma16816(float* c, const u32* a, const u32* b) {
    asm volatile(
        "mma.sync.aligned.m16n8k16.row.col.f32.bf16.bf16.f32 "
        "{%0,%1,%2,%3}, {%4,%5,%6,%7}, {%8,%9}, {%0,%1,%2,%3};"
        : "+f"(c[0]), "+f"(c[1]), "+f"(c[2]), "+f"(c[3])
        : "r"(a[0]), "r"(a[1]), "r"(a[2]), "r"(a[3]), "r"(b[0]), "r"(b[1]));
}
__device__ __forceinline__ void ldm_x4(u32* r, u32 addr) {
    asm volatile("ldmatrix.sync.aligned.m8n8.x4.shared.b16 {%0,%1,%2,%3}, [%4];"
                 : "=r"(r[0]), "=r"(r[1]), "=r"(r[2]), "=r"(r[3]) : "r"(addr));
}
__device__ __forceinline__ void cpasync16(u32 dst, const void* src) {
    asm volatile("cp.async.cg.shared.global [%0], [%1], 16;" :: "r"(dst), "l"(src));
}

// ---------------- prep kernels ----------------
__global__ void prep_b1eff(const float* __restrict__ W1, const float* __restrict__ b1,
                           const float* __restrict__ coeffs) {
    int n = threadIdx.x;
    float s = 0.f;
    #pragma unroll 8
    for (int j = 0; j < HD; j++) s += W1[j * MEMH + n];
    g_b1eff[n] = b1[n] + coeffs[0] * s;
}
__global__ void split_hs(const float* __restrict__ hs) {
    int i4 = blockIdx.x * 256 + threadIdx.x;
    float4 v = ((const float4*)hs)[i4];
    u32 h0, l0, h1, l1;
    split2(v.x, v.y, h0, l0);
    split2(v.z, v.w, h1, l1);
    ((u32*)g_hs_hi)[i4 * 2] = h0; ((u32*)g_hs_hi)[i4 * 2 + 1] = h1;
    ((u32*)g_hs_lo)[i4 * 2] = l0; ((u32*)g_hs_lo)[i4 * 2 + 1] = l1;
}
__global__ void split_wqt(const float* __restrict__ Wq) {
    int idx = blockIdx.x * 256 + threadIdx.x;
    int n = idx / HIDDEN, k = idx - n * HIDDEN;
    float v = Wq[(size_t)k * HIDDEN + n];
    __nv_bfloat16 hi = __float2bfloat16(v);
    g_wqt_hi[idx] = hi;
    g_wqt_lo[idx] = __float2bfloat16(v - __bfloat162float(hi));
}
__global__ void split_w1t(const float* __restrict__ W1) {
    int idx = blockIdx.x * 256 + threadIdx.x;
    int n = idx / KP, k = idx - n * KP;
    float v = W1[(size_t)(HD + k) * MEMH + n];
    __nv_bfloat16 hi = __float2bfloat16(v);
    g_w1t_hi[idx] = hi;
    g_w1t_lo[idx] = __float2bfloat16(v - __bfloat162float(hi));
}
__global__ void split_w2t(const float* __restrict__ W2) {
    int idx = blockIdx.x * 256 + threadIdx.x;
    int n = idx >> 9, k = idx & 511;
    float v = W2[(size_t)k * 256 + n];
    __nv_bfloat16 hi = __float2bfloat16(v);
    g_w2t_hi[idx] = hi;
    g_w2t_lo[idx] = __float2bfloat16(v - __bfloat162float(hi));
}

// ---------------- GEMM1: q = clip(hs@Wq), split-3 ---------------------------
__global__ __launch_bounds__(256) void gemm1_kernel() {
    constexpr int BM = 128, BN = 128, BK = 32, NT = 8;
    constexpr int SA = 20;
    constexpr int TILE_A = BM * SA, TILE_B = BN * SA;
    constexpr int STAGE = 2 * TILE_A + 2 * TILE_B;
    constexpr int K = HIDDEN, NIT = K / BK;

    extern __shared__ u32 smem[];
    const u32 sbase = smem_u32(smem);
    const int tid = threadIdx.x, wid = tid >> 5, lane = tid & 31;
    const int g = lane >> 2, tg = lane & 3;
    const int m0 = blockIdx.x * BM, n0 = blockIdx.y * BN;
    const int warpM = wid & 3, warpN = wid >> 2;

    // per-thread ldmatrix base offsets (bytes), kt adds 32 bytes
    const u32 aoff0 = (u32)(((warpM * 32 + (lane & 15)) * SA + (lane >> 4) * 4) * 4);
    const u32 boff0 = (u32)(((warpN * 64 + (lane & 7) + ((lane & 16) ? 8 : 0)) * SA
                             + ((lane & 8) ? 4 : 0)) * 4);

    float acc[2][NT][4];
    #pragma unroll
    for (int mt = 0; mt < 2; mt++)
        #pragma unroll
        for (int nt = 0; nt < NT; nt++)
            #pragma unroll
            for (int j = 0; j < 4; j++) acc[mt][nt][j] = 0.f;

    auto load_stage = [&](int s, int k0) {
        const u32 stb = sbase + (u32)s * STAGE * 4;
        #pragma unroll
        for (int t = 0; t < 2; t++) {
            const __nv_bfloat16* src = t ? g_hs_lo : g_hs_hi;
            #pragma unroll
            for (int idx = 0; idx < 2; idx++) {
                int l = tid + idx * 256;
                int r = l >> 2, c = l & 3;
                cpasync16(stb + (u32)(t * TILE_A + r * SA) * 4 + c * 16,
                          src + (size_t)(m0 + r) * K + k0 + c * 8);
            }
        }
        #pragma unroll
        for (int t = 0; t < 2; t++) {
            const __nv_bfloat16* src = t ? g_wqt_lo : g_wqt_hi;
            #pragma unroll
            for (int idx = 0; idx < 2; idx++) {
                int l = tid + idx * 256;
                int r = l >> 2, c = l & 3;
                cpasync16(stb + (u32)(2 * TILE_A + t * TILE_B + r * SA) * 4 + c * 16,
                          src + (size_t)(n0 + r) * K + k0 + c * 8);
            }
        }
        asm volatile("cp.async.commit_group;");
    };

    load_stage(0, 0);
    for (int it = 0; it < NIT; it++) {
        if (it + 1 < NIT) {
            load_stage((it + 1) & 1, (it + 1) * BK);
            asm volatile("cp.async.wait_group %0;" :: "n"(1));
        } else {
            asm volatile("cp.async.wait_group %0;" :: "n"(0));
        }
        __syncthreads();
        const u32 stb = sbase + (u32)(it & 1) * STAGE * 4;
        #pragma unroll
        for (int kt = 0; kt < 2; kt++) {
            const u32 kadd = (u32)kt * 32;
            u32 ah[2][4], al[2][4];
            ldm_x4(ah[0], stb + aoff0 + kadd);
            ldm_x4(ah[1], stb + aoff0 + kadd + 16 * SA * 4);
            ldm_x4(al[0], stb + TILE_A * 4 + aoff0 + kadd);
            ldm_x4(al[1], stb + TILE_A * 4 + aoff0 + kadd + 16 * SA * 4);
            u32 bh[NT][2], bl[NT][2];
            #pragma unroll
            for (int p = 0; p < 4; p++) {
                ldm_x4(&bh[p * 2][0], stb + 2 * TILE_A * 4 + boff0 + kadd + (u32)p * 16 * SA * 4);
                ldm_x4(&bl[p * 2][0], stb + (2 * TILE_A + TILE_B) * 4 + boff0 + kadd
                                          + (u32)p * 16 * SA * 4);
            }
            #pragma unroll
            for (int mt = 0; mt < 2; mt++)
                #pragma unroll
                for (int nt = 0; nt < NT; nt++) mma16816(acc[mt][nt], ah[mt], bh[nt]);
            #pragma unroll
            for (int mt = 0; mt < 2; mt++)
                #pragma unroll
                for (int nt = 0; nt < NT; nt++) mma16816(acc[mt][nt], ah[mt], bl[nt]);
            #pragma unroll
            for (int mt = 0; mt < 2; mt++)
                #pragma unroll
                for (int nt = 0; nt < NT; nt++) mma16816(acc[mt][nt], al[mt], bh[nt]);
        }
        __syncthreads();
    }

    #pragma unroll
    for (int mt = 0; mt < 2; mt++)
        #pragma unroll
        for (int nt = 0; nt < NT; nt++)
            #pragma unroll
            for (int h = 0; h < 2; h++) {
                int row = m0 + warpM * 32 + mt * 16 + g + h * 8;
                int col = n0 + warpN * NT * 8 + nt * 8 + tg * 2;
                float v0 = fminf(fmaxf(acc[mt][nt][h * 2],     -10.f), 10.f);
                float v1 = fminf(fmaxf(acc[mt][nt][h * 2 + 1], -10.f), 10.f);
                *(float2*)&g_qs[(size_t)row * HIDDEN + col] = make_float2(v0, v1);
            }
}

// ---------------- fused MLP kernel ----------------
#define SP 100
#define SH 36
#define O_PHI   0                          // 128*100
#define O_PLO   12800
#define O_B2HI  25600                      // 64*100
#define O_B2LO  32000
#define O_HHI   38400                      // 128*36
#define O_HLO   43008
#define O_B3    47616                      // 2 parities x (hi 2304 + lo 2304)
#define SMEM_FUSED_U32 56832               // * 4 = 227328 B

__global__ __launch_bounds__(256) void mlp_fused(const float* __restrict__ coeffs,
                                                 const float* __restrict__ b2,
                                                 float* __restrict__ outf) {
    extern __shared__ u32 smem[];
    const u32 sbase = smem_u32(smem);
    const int tid = threadIdx.x, wid = tid >> 5, lane = tid & 31;
    const int g = lane >> 2, tg = lane & 3;
    const int r0 = blockIdx.x * 128;
    const int warpM = wid & 3, warpN = wid >> 2;   // warpN in {0,1}

    // ldmatrix per-thread base offsets (bytes)
    const u32 aP0 = (u32)(((warpM * 32 + (lane & 15)) * SP + (lane >> 4) * 4) * 4);
    const u32 bP0 = (u32)(((warpN * 32 + (lane & 7) + ((lane & 16) ? 8 : 0)) * SP
                           + ((lane & 8) ? 4 : 0)) * 4);
    const u32 aH0 = (u32)(((warpM * 32 + (lane & 15)) * SH + (lane >> 4) * 4) * 4);
    const u32 bH0 = (u32)(((warpN * 32 + (lane & 7) + ((lane & 16) ? 8 : 0)) * SH
                           + ((lane & 8) ? 4 : 0)) * 4);

    auto load_b2 = [&](int c) {
        #pragma unroll
        for (int t = 0; t < 2; t++) {
            const __nv_bfloat16* src = t ? g_w1t_lo : g_w1t_hi;
            u32 base = sbase + (t ? O_B2LO : O_B2HI) * 4;
            #pragma unroll
            for (int i = 0; i < 6; i++) {
                int l = tid + i * 256;                 // 64 rows * 24 chunks
                int n = l / 24, ch = l - n * 24;
                cpasync16(base + (u32)n * (SP * 4) + ch * 16,
                          src + (size_t)(c * 64 + n) * KP + ch * 8);
            }
        }
    };
    auto load_b3 = [&](int c, int par) {
        #pragma unroll
        for (int t = 0; t < 2; t++) {
            const __nv_bfloat16* src = t ? g_w2t_lo : g_w2t_hi;
            u32 base = sbase + (O_B3 + par * 4608 + t * 2304) * 4;
            #pragma unroll
            for (int i = 0; i < 2; i++) {
                int l = tid + i * 256;                 // 64 rows * 8 chunks
                int n = l >> 3, ch = l & 7;
                cpasync16(base + (u32)n * (SH * 4) + ch * 16,
                          src + (size_t)n * MEMH + c * 64 + ch * 8);
            }
        }
    };

    load_b2(0);
    load_b3(0, 0);
    asm volatile("cp.async.commit_group;");

    // ---- poly expansion: q -> P hi/lo in smem
    {
        const float c1 = coeffs[1], c2 = coeffs[2], c3 = coeffs[3];
        const float2* qb = (const float2*)(g_qs + (size_t)r0 * HD);
        #pragma unroll
        for (int i = 0; i < 16; i++) {
            int l = tid + i * 256;                     // 128 rows * 32 pairs
            int r = l >> 5, d2 = l & 31;
            float2 x = qb[l];
            float xa2 = x.x * x.x, xb2 = x.y * x.y;
            float pa[3] = {c1 * x.x, c2 * xa2, c3 * xa2 * x.x};
            float pb[3] = {c1 * x.y, c2 * xb2, c3 * xb2 * x.y};
            #pragma unroll
            for (int fi = 0; fi < 3; fi++) {
                float a = fminf(fmaxf(pa[fi], -1e6f), 1e6f);
                float b = fminf(fmaxf(pb[fi], -1e6f), 1e6f);
                u32 hi, lo; split2(a, b, hi, lo);
                smem[O_PHI + r * SP + fi * 32 + d2] = hi;
                smem[O_PLO + r * SP + fi * 32 + d2] = lo;
            }
        }
    }
    asm volatile("cp.async.wait_group %0;" :: "n"(0));
    __syncthreads();

    float acc3[2][4][4];
    #pragma unroll
    for (int mt = 0; mt < 2; mt++)
        #pragma unroll
        for (int nt = 0; nt < 4; nt++)
            #pragma unroll
            for (int j = 0; j < 4; j++) acc3[mt][nt][j] = 0.f;

    for (int c = 0; c < 8; c++) {
        // ---- GEMM2: [128 x 64] = P[128 x 192] * B2^T, split-3
        float acc2[2][4][4];
        #pragma unroll
        for (int mt = 0; mt < 2; mt++)
            #pragma unroll
            for (int nt = 0; nt < 4; nt++)
                #pragma unroll
                for (int j = 0; j < 4; j++) acc2[mt][nt][j] = 0.f;

        #pragma unroll
        for (int kt = 0; kt < 12; kt++) {
            const u32 kadd = (u32)kt * 32;
            u32 ah[2][4], al[2][4];
            ldm_x4(ah[0], sbase + O_PHI * 4 + aP0 + kadd);
            ldm_x4(ah[1], sbase + O_PHI * 4 + aP0 + kadd + 16 * SP * 4);
            ldm_x4(al[0], sbase + O_PLO * 4 + aP0 + kadd);
            ldm_x4(al[1], sbase + O_PLO * 4 + aP0 + kadd + 16 * SP * 4);
            u32 bh[4][2], bl[4][2];
            ldm_x4(&bh[0][0], sbase + O_B2HI * 4 + bP0 + kadd);
            ldm_x4(&bh[2][0], sbase + O_B2HI * 4 + bP0 + kadd + 16 * SP * 4);
            ldm_x4(&bl[0][0], sbase + O_B2LO * 4 + bP0 + kadd);
            ldm_x4(&bl[2][0], sbase + O_B2LO * 4 + bP0 + kadd + 16 * SP * 4);
            #pragma unroll
            for (int mt = 0; mt < 2; mt++)
                #pragma unroll
                for (int nt = 0; nt < 4; nt++) mma16816(acc2[mt][nt], ah[mt], bh[nt]);
            #pragma unroll
            for (int mt = 0; mt < 2; mt++)
                #pragma unroll
                for (int nt = 0; nt < 4; nt++) mma16816(acc2[mt][nt], ah[mt], bl[nt]);
            #pragma unroll
            for (int mt = 0; mt < 2; mt++)
                #pragma unroll
                for (int nt = 0; nt < 4; nt++) mma16816(acc2[mt][nt], al[mt], bh[nt]);
        }
        __syncthreads();                     // B2 consumed; H(c-1) consumed earlier

        // ---- relu + split -> H smem
        #pragma unroll
        for (int mt = 0; mt < 2; mt++)
            #pragma unroll
            for (int nt = 0; nt < 4; nt++) {
                int colg = c * 64 + warpN * 32 + nt * 8 + tg * 2;
                float2 bb = *(const float2*)&g_b1eff[colg];
                #pragma unroll
                for (int h = 0; h < 2; h++) {
                    int row = warpM * 32 + mt * 16 + g + h * 8;
                    int cu  = warpN * 16 + nt * 4 + tg;
                    float v0 = fmaxf(acc2[mt][nt][h * 2]     + bb.x, 0.f);
                    float v1 = fmaxf(acc2[mt][nt][h * 2 + 1] + bb.y, 0.f);
                    u32 hi, lo; split2(v0, v1, hi, lo);
                    smem[O_HHI + row * SH + cu] = hi;
                    smem[O_HLO + row * SH + cu] = lo;
                }
            }
        if (c < 7) {
            load_b2(c + 1);
            load_b3(c + 1, (c + 1) & 1);
            asm volatile("cp.async.commit_group;");
        }
        __syncthreads();                     // H visible

        // ---- GEMM3 accumulate: acc3 += H[128 x 64] * B3^T (overlaps cp.async)
        const u32 b3hB = sbase + (u32)(O_B3 + (c & 1) * 4608) * 4;
        const u32 b3lB = b3hB + 2304 * 4;
        #pragma unroll
        for (int kt = 0; kt < 4; kt++) {
            const u32 kadd = (u32)kt * 32;
            u32 ah[2][4], al[2][4];
            ldm_x4(ah[0], sbase + O_HHI * 4 + aH0 + kadd);
            ldm_x4(ah[1], sbase + O_HHI * 4 + aH0 + kadd + 16 * SH * 4);
            ldm_x4(al[0], sbase + O_HLO * 4 + aH0 + kadd);
            ldm_x4(al[1], sbase + O_HLO * 4 + aH0 + kadd + 16 * SH * 4);
            u32 bh[4][2], bl[4][2];
            ldm_x4(&bh[0][0], b3hB + bH0 + kadd);
            ldm_x4(&bh[2][0], b3hB + bH0 + kadd + 16 * SH * 4);
            ldm_x4(&bl[0][0], b3lB + bH0 + kadd);
            ldm_x4(&bl[2][0], b3lB + bH0 + kadd + 16 * SH * 4);
            #pragma unroll
            for (int mt = 0; mt < 2; mt++)
                #pragma unroll
                for (int nt = 0; nt < 4; nt++) mma16816(acc3[mt][nt], ah[mt], bh[nt]);
            #pragma unroll
            for (int mt = 0; mt < 2; mt++)
                #pragma unroll
                for (int nt = 0; nt < 4; nt++) mma16816(acc3[mt][nt], ah[mt], bl[nt]);
            #pragma unroll
            for (int mt = 0; mt < 2; mt++)
                #pragma unroll
                for (int nt = 0; nt < 4; nt++) mma16816(acc3[mt][nt], al[mt], bh[nt]);
        }
        if (c < 7) {
            asm volatile("cp.async.wait_group %0;" :: "n"(0));
            __syncthreads();                 // next B2/B3 ready; GEMM3 done before H overwrite
        }
    }

    // ---- output: + b2
    #pragma unroll
    for (int mt = 0; mt < 2; mt++)
        #pragma unroll
        for (int nt = 0; nt < 4; nt++) {
            int col = warpN * 32 + nt * 8 + tg * 2;
            float2 bb = *(const float2*)&b2[col];
            #pragma unroll
            for (int h = 0; h < 2; h++) {
                int row = r0 + warpM * 32 + mt * 16 + g + h * 8;
                float2 o = make_float2(acc3[mt][nt][h * 2] + bb.x,
                                       acc3[mt][nt][h * 2 + 1] + bb.y);
                *(float2*)&outf[(size_t)row * HD + col] = o;
            }
        }
}

// ---------------------------------------------------------------------------
extern "C" void kernel_launch(void* const* d_in, const int* in_sizes, int n_in,
                              void* d_out, int out_size) {
    const float* hs     = (const float*)d_in[0];
    const float* Wq     = (const float*)d_in[1];
    const float* coeffs = (const float*)d_in[2];
    const float* W1     = (const float*)d_in[3];
    const float* b1     = (const float*)d_in[4];
    const float* W2     = (const float*)d_in[5];
    const float* b2     = (const float*)d_in[6];
    float* out = (float*)d_out;

    prep_b1eff<<<1, MEMH>>>(W1, b1, coeffs);
    split_hs<<<(TOKENS * HIDDEN / 4) / 256, 256>>>(hs);
    split_wqt<<<(HIDDEN * HIDDEN) / 256, 256>>>(Wq);
    split_w1t<<<(MEMH * KP) / 256, 256>>>(W1);
    split_w2t<<<(HD * MEMH) / 256, 256>>>(W2);

    constexpr int SM1 = (2 * 128 * 20 + 2 * 128 * 20) * 4 * 2;   // 81920 B
    constexpr int SMF = SMEM_FUSED_U32 * 4;                      // 227328 B
    cudaFuncSetAttribute(gemm1_kernel, cudaFuncAttributeMaxDynamicSharedMemorySize, SM1);
    cudaFuncSetAttribute(mlp_fused,    cudaFuncAttributeMaxDynamicSharedMemorySize, SMF);

    gemm1_kernel<<<dim3(TOKENS / 128, HIDDEN / 128), 256, SM1>>>();
    mlp_fused<<<FLATR / 128, 256, SMF>>>(coeffs, b2, out);
}

// round 6
// speedup vs baseline: 1.9147x; 1.9147x over previous
#include <cuda_runtime.h>
#include <cuda_bf16.h>
#include <cuda_fp16.h>

// ---------------------------------------------------------------------------
// AtlasAttention, legacy mma.sync fp16 split-2 (A-side), fused MLP.
//   Each GEMM: C = Af*B + Ar*B   (A = Af + Ar in fp16, B single fp16,
//   fp32 accum; dropped A*Br term ~1.4e-4 rel).  2/3 the MMAs of bf16 split-3.
//   GEMM1: q = clip(hs@Wq) -> g_qs (fp32)
//   Fused per 128 flat rows: poly(q)->P(f,r) smem; 8 chunks of 64 cols:
//       GEMM2 (P x W1chunk) -> relu+split -> H(f,r) smem -> GEMM3 accum in regs
//   Exact folds: b1eff (const poly block), W2[:, :64] slice.
// ---------------------------------------------------------------------------

typedef unsigned int u32;

#define TOKENS 8192
#define HIDDEN 768
#define FLATR  98304
#define MEMH   512
#define KP     192
#define HD     64

__device__ __align__(16) __half g_hs_f[TOKENS * HIDDEN];
__device__ __align__(16) __half g_hs_r[TOKENS * HIDDEN];
__device__ __align__(16) __half g_wqt[HIDDEN * HIDDEN];   // [n][k] fp16
__device__ __align__(16) __half g_w1t[MEMH * KP];         // [n=512][k=192]
__device__ __align__(16) __half g_w2t[HD * MEMH];         // [n=64][k=512]
__device__ float g_qs[(size_t)FLATR * HD];                // clipped q
__device__ float g_b1eff[MEMH];

// ---------------- helpers ----------------
__device__ __forceinline__ u32 smem_u32(const void* p) {
    u32 a; asm("{ .reg .u64 t; cvta.to.shared.u64 t, %1; cvt.u32.u64 %0, t; }"
               : "=r"(a) : "l"(p)); return a;
}
__device__ __forceinline__ u32 pack_h(__half a, __half b) {
    return (u32)__half_as_ushort(a) | ((u32)__half_as_ushort(b) << 16);
}
// split v into fp16 main + fp16 residual, packed pairwise
__device__ __forceinline__ void split2h(float v0, float v1, u32 &f, u32 &r) {
    __half h0 = __float2half_rn(v0), h1 = __float2half_rn(v1);
    __half r0 = __float2half_rn(v0 - __half2float(h0));
    __half r1 = __float2half_rn(v1 - __half2float(h1));
    f = pack_h(h0, h1); r = pack_h(r0, r1);
}
__device__ __forceinline__ void mma16816(float* c, const u32* a, const u32* b) {
    asm volatile(
        "mma.sync.aligned.m16n8k16.row.col.f32.f16.f16.f32 "
        "{%0,%1,%2,%3}, {%4,%5,%6,%7}, {%8,%9}, {%0,%1,%2,%3};"
        : "+f"(c[0]), "+f"(c[1]), "+f"(c[2]), "+f"(c[3])
        : "r"(a[0]), "r"(a[1]), "r"(a[2]), "r"(a[3]), "r"(b[0]), "r"(b[1]));
}
__device__ __forceinline__ void cpasync16(u32 dst, const void* src) {
    asm volatile("cp.async.cg.shared.global [%0], [%1], 16;" :: "r"(dst), "l"(src));
}

// ---------------- prep kernels ----------------
__global__ void prep_b1eff(const float* __restrict__ W1, const float* __restrict__ b1,
                           const float* __restrict__ coeffs) {
    int n = threadIdx.x;
    float s = 0.f;
    #pragma unroll 8
    for (int j = 0; j < HD; j++) s += W1[j * MEMH + n];
    g_b1eff[n] = b1[n] + coeffs[0] * s;
}
__global__ void split_hs(const float* __restrict__ hs) {
    int i4 = blockIdx.x * 256 + threadIdx.x;
    float4 v = ((const float4*)hs)[i4];
    u32 f0, r0, f1, r1;
    split2h(v.x, v.y, f0, r0);
    split2h(v.z, v.w, f1, r1);
    ((u32*)g_hs_f)[i4 * 2] = f0; ((u32*)g_hs_f)[i4 * 2 + 1] = f1;
    ((u32*)g_hs_r)[i4 * 2] = r0; ((u32*)g_hs_r)[i4 * 2 + 1] = r1;
}
__global__ void cvt_wqt(const float* __restrict__ Wq) {
    int idx = blockIdx.x * 256 + threadIdx.x;
    int n = idx / HIDDEN, k = idx - n * HIDDEN;
    g_wqt[idx] = __float2half_rn(Wq[(size_t)k * HIDDEN + n]);
}
__global__ void cvt_w1t(const float* __restrict__ W1) {
    int idx = blockIdx.x * 256 + threadIdx.x;
    int n = idx / KP, k = idx - n * KP;
    g_w1t[idx] = __float2half_rn(W1[(size_t)(HD + k) * MEMH + n]);
}
__global__ void cvt_w2t(const float* __restrict__ W2) {
    int idx = blockIdx.x * 256 + threadIdx.x;
    int n = idx >> 9, k = idx & 511;
    g_w2t[idx] = __float2half_rn(W2[(size_t)k * 256 + n]);
}

// ---------------- GEMM1: q = clip(hs@Wq), fp16 split-2 ----------------------
__global__ __launch_bounds__(256) void gemm1_kernel() {
    constexpr int BM = 128, BN = 128, BK = 32, NT = 8;
    constexpr int SA = 20;
    constexpr int TILE_A = BM * SA, TILE_B = BN * SA;
    constexpr int STAGE = 2 * TILE_A + TILE_B;
    constexpr int K = HIDDEN, NIT = K / BK;

    extern __shared__ u32 smem[];
    const u32 sbase = smem_u32(smem);
    const int tid = threadIdx.x, wid = tid >> 5, lane = tid & 31;
    const int g = lane >> 2, tg = lane & 3;
    const int m0 = blockIdx.x * BM, n0 = blockIdx.y * BN;
    const int warpM = wid & 3, warpN = wid >> 2;

    float acc[2][NT][4];
    #pragma unroll
    for (int mt = 0; mt < 2; mt++)
        #pragma unroll
        for (int nt = 0; nt < NT; nt++)
            #pragma unroll
            for (int j = 0; j < 4; j++) acc[mt][nt][j] = 0.f;

    auto load_stage = [&](int s, int k0) {
        const u32 stb = sbase + (u32)s * STAGE * 4;
        #pragma unroll
        for (int t = 0; t < 2; t++) {
            const __half* src = t ? g_hs_r : g_hs_f;
            #pragma unroll
            for (int idx = 0; idx < 2; idx++) {
                int l = tid + idx * 256;
                int r = l >> 2, c = l & 3;
                cpasync16(stb + (u32)(t * TILE_A + r * SA) * 4 + c * 16,
                          src + (size_t)(m0 + r) * K + k0 + c * 8);
            }
        }
        #pragma unroll
        for (int idx = 0; idx < 2; idx++) {
            int l = tid + idx * 256;
            int r = l >> 2, c = l & 3;
            cpasync16(stb + (u32)(2 * TILE_A + r * SA) * 4 + c * 16,
                      g_wqt + (size_t)(n0 + r) * K + k0 + c * 8);
        }
        asm volatile("cp.async.commit_group;");
    };

    load_stage(0, 0);
    for (int it = 0; it < NIT; it++) {
        if (it + 1 < NIT) {
            load_stage((it + 1) & 1, (it + 1) * BK);
            asm volatile("cp.async.wait_group %0;" :: "n"(1));
        } else {
            asm volatile("cp.async.wait_group %0;" :: "n"(0));
        }
        __syncthreads();
        const u32* S = smem + (it & 1) * STAGE;
        #pragma unroll
        for (int kt = 0; kt < 2; kt++) {
            u32 af[2][4], ar[2][4];
            #pragma unroll
            for (int mt = 0; mt < 2; mt++) {
                int off = (warpM * 32 + mt * 16 + g) * SA + kt * 8 + tg;
                af[mt][0] = S[off];       af[mt][1] = S[off + 8 * SA];
                af[mt][2] = S[off + 4];   af[mt][3] = S[off + 8 * SA + 4];
                const u32* SR = S + TILE_A;
                ar[mt][0] = SR[off];      ar[mt][1] = SR[off + 8 * SA];
                ar[mt][2] = SR[off + 4];  ar[mt][3] = SR[off + 8 * SA + 4];
            }
            u32 bv[NT][2];
            #pragma unroll
            for (int nt = 0; nt < NT; nt++) {
                int off = (warpN * NT * 8 + nt * 8 + g) * SA + kt * 8 + tg;
                const u32* SB = S + 2 * TILE_A;
                bv[nt][0] = SB[off]; bv[nt][1] = SB[off + 4];
            }
            #pragma unroll
            for (int mt = 0; mt < 2; mt++)
                #pragma unroll
                for (int nt = 0; nt < NT; nt++) mma16816(acc[mt][nt], af[mt], bv[nt]);
            #pragma unroll
            for (int mt = 0; mt < 2; mt++)
                #pragma unroll
                for (int nt = 0; nt < NT; nt++) mma16816(acc[mt][nt], ar[mt], bv[nt]);
        }
        __syncthreads();
    }

    #pragma unroll
    for (int mt = 0; mt < 2; mt++)
        #pragma unroll
        for (int nt = 0; nt < NT; nt++)
            #pragma unroll
            for (int h = 0; h < 2; h++) {
                int row = m0 + warpM * 32 + mt * 16 + g + h * 8;
                int col = n0 + warpN * NT * 8 + nt * 8 + tg * 2;
                float v0 = fminf(fmaxf(acc[mt][nt][h * 2],     -10.f), 10.f);
                float v1 = fminf(fmaxf(acc[mt][nt][h * 2 + 1], -10.f), 10.f);
                *(float2*)&g_qs[(size_t)row * HIDDEN + col] = make_float2(v0, v1);
            }
}

// ---------------- fused MLP kernel ----------------
#define SP 100
#define SH 36
#define O_PF   0                           // 128*100
#define O_PR   12800
#define O_B2   25600                       // 64*100
#define O_HF   32000                       // 128*36
#define O_HR   36608
#define O_B3   41216                       // 2 parities x 2304
#define SMEM_FUSED_U32 45824               // * 4 = 183296 B

__global__ __launch_bounds__(256) void mlp_fused(const float* __restrict__ coeffs,
                                                 const float* __restrict__ b2,
                                                 float* __restrict__ outf) {
    extern __shared__ u32 smem[];
    const u32 sbase = smem_u32(smem);
    const int tid = threadIdx.x, wid = tid >> 5, lane = tid & 31;
    const int g = lane >> 2, tg = lane & 3;
    const int r0 = blockIdx.x * 128;
    const int warpM = wid & 3, warpN = wid >> 2;   // warpN in {0,1}

    auto load_b2 = [&](int c) {
        u32 base = sbase + O_B2 * 4;
        #pragma unroll
        for (int i = 0; i < 6; i++) {
            int l = tid + i * 256;                 // 64 rows * 24 chunks
            int n = l / 24, ch = l - n * 24;
            cpasync16(base + (u32)n * (SP * 4) + ch * 16,
                      g_w1t + (size_t)(c * 64 + n) * KP + ch * 8);
        }
    };
    auto load_b3 = [&](int c, int par) {
        u32 base = sbase + (O_B3 + par * 2304) * 4;
        #pragma unroll
        for (int i = 0; i < 2; i++) {
            int l = tid + i * 256;                 // 64 rows * 8 chunks
            int n = l >> 3, ch = l & 7;
            cpasync16(base + (u32)n * (SH * 4) + ch * 16,
                      g_w2t + (size_t)n * MEMH + c * 64 + ch * 8);
        }
    };

    load_b2(0);
    load_b3(0, 0);
    asm volatile("cp.async.commit_group;");

    // ---- poly expansion: q -> P f/r in smem
    {
        const float c1 = coeffs[1], c2 = coeffs[2], c3 = coeffs[3];
        const float2* qb = (const float2*)(g_qs + (size_t)r0 * HD);
        #pragma unroll
        for (int i = 0; i < 16; i++) {
            int l = tid + i * 256;                 // 128 rows * 32 pairs
            int r = l >> 5, d2 = l & 31;
            float2 x = qb[l];
            float xa2 = x.x * x.x, xb2 = x.y * x.y;
            float pa[3] = {c1 * x.x, c2 * xa2, c3 * xa2 * x.x};
            float pb[3] = {c1 * x.y, c2 * xb2, c3 * xb2 * x.y};
            #pragma unroll
            for (int fi = 0; fi < 3; fi++) {
                float a = fminf(fmaxf(pa[fi], -1e6f), 1e6f);
                float b = fminf(fmaxf(pb[fi], -1e6f), 1e6f);
                u32 f, rr; split2h(a, b, f, rr);
                smem[O_PF + r * SP + fi * 32 + d2] = f;
                smem[O_PR + r * SP + fi * 32 + d2] = rr;
            }
        }
    }
    asm volatile("cp.async.wait_group %0;" :: "n"(0));
    __syncthreads();

    float acc3[2][4][4];
    #pragma unroll
    for (int mt = 0; mt < 2; mt++)
        #pragma unroll
        for (int nt = 0; nt < 4; nt++)
            #pragma unroll
            for (int j = 0; j < 4; j++) acc3[mt][nt][j] = 0.f;

    for (int c = 0; c < 8; c++) {
        // ---- GEMM2: [128 x 64] = P[128 x 192] * B2^T, fp16 split-2
        float acc2[2][4][4];
        #pragma unroll
        for (int mt = 0; mt < 2; mt++)
            #pragma unroll
            for (int nt = 0; nt < 4; nt++)
                #pragma unroll
                for (int j = 0; j < 4; j++) acc2[mt][nt][j] = 0.f;

        #pragma unroll
        for (int kt = 0; kt < 12; kt++) {
            u32 af[2][4], ar[2][4];
            #pragma unroll
            for (int mt = 0; mt < 2; mt++) {
                int off = (warpM * 32 + mt * 16 + g) * SP + kt * 8 + tg;
                af[mt][0] = smem[O_PF + off];        af[mt][1] = smem[O_PF + off + 8 * SP];
                af[mt][2] = smem[O_PF + off + 4];    af[mt][3] = smem[O_PF + off + 8 * SP + 4];
                ar[mt][0] = smem[O_PR + off];        ar[mt][1] = smem[O_PR + off + 8 * SP];
                ar[mt][2] = smem[O_PR + off + 4];    ar[mt][3] = smem[O_PR + off + 8 * SP + 4];
            }
            u32 bv[4][2];
            #pragma unroll
            for (int nt = 0; nt < 4; nt++) {
                int off = (warpN * 32 + nt * 8 + g) * SP + kt * 8 + tg;
                bv[nt][0] = smem[O_B2 + off]; bv[nt][1] = smem[O_B2 + off + 4];
            }
            #pragma unroll
            for (int mt = 0; mt < 2; mt++)
                #pragma unroll
                for (int nt = 0; nt < 4; nt++) mma16816(acc2[mt][nt], af[mt], bv[nt]);
            #pragma unroll
            for (int mt = 0; mt < 2; mt++)
                #pragma unroll
                for (int nt = 0; nt < 4; nt++) mma16816(acc2[mt][nt], ar[mt], bv[nt]);
        }
        __syncthreads();                     // B2 consumed; H(c-1) consumed earlier

        // ---- relu + split -> H smem
        #pragma unroll
        for (int mt = 0; mt < 2; mt++)
            #pragma unroll
            for (int nt = 0; nt < 4; nt++) {
                int colg = c * 64 + warpN * 32 + nt * 8 + tg * 2;
                float2 bb = *(const float2*)&g_b1eff[colg];
                #pragma unroll
                for (int h = 0; h < 2; h++) {
                    int row = warpM * 32 + mt * 16 + g + h * 8;
                    int cu  = warpN * 16 + nt * 4 + tg;
                    float v0 = fmaxf(acc2[mt][nt][h * 2]     + bb.x, 0.f);
                    float v1 = fmaxf(acc2[mt][nt][h * 2 + 1] + bb.y, 0.f);
                    u32 f, rr; split2h(v0, v1, f, rr);
                    smem[O_HF + row * SH + cu] = f;
                    smem[O_HR + row * SH + cu] = rr;
                }
            }
        if (c < 7) {
            load_b2(c + 1);
            load_b3(c + 1, (c + 1) & 1);
            asm volatile("cp.async.commit_group;");
        }
        __syncthreads();                     // H visible

        // ---- GEMM3 accumulate: acc3 += H[128 x 64] * B3^T (overlaps cp.async)
        const int b3o = O_B3 + (c & 1) * 2304;
        #pragma unroll
        for (int kt = 0; kt < 4; kt++) {
            u32 af[2][4], ar[2][4];
            #pragma unroll
            for (int mt = 0; mt < 2; mt++) {
                int off = (warpM * 32 + mt * 16 + g) * SH + kt * 8 + tg;
                af[mt][0] = smem[O_HF + off];        af[mt][1] = smem[O_HF + off + 8 * SH];
                af[mt][2] = smem[O_HF + off + 4];    af[mt][3] = smem[O_HF + off + 8 * SH + 4];
                ar[mt][0] = smem[O_HR + off];        ar[mt][1] = smem[O_HR + off + 8 * SH];
                ar[mt][2] = smem[O_HR + off + 4];    ar[mt][3] = smem[O_HR + off + 8 * SH + 4];
            }
            u32 bv[4][2];
            #pragma unroll
            for (int nt = 0; nt < 4; nt++) {
                int off = (warpN * 32 + nt * 8 + g) * SH + kt * 8 + tg;
                bv[nt][0] = smem[b3o + off]; bv[nt][1] = smem[b3o + off + 4];
            }
            #pragma unroll
            for (int mt = 0; mt < 2; mt++)
                #pragma unroll
                for (int nt = 0; nt < 4; nt++) mma16816(acc3[mt][nt], af[mt], bv[nt]);
            #pragma unroll
            for (int mt = 0; mt < 2; mt++)
                #pragma unroll
                for (int nt = 0; nt < 4; nt++) mma16816(acc3[mt][nt], ar[mt], bv[nt]);
        }
        if (c < 7) {
            asm volatile("cp.async.wait_group %0;" :: "n"(0));
            __syncthreads();                 // next B2/B3 ready; GEMM3 done before H overwrite
        }
    }

    // ---- output: + b2
    #pragma unroll
    for (int mt = 0; mt < 2; mt++)
        #pragma unroll
        for (int nt = 0; nt < 4; nt++) {
            int col = warpN * 32 + nt * 8 + tg * 2;
            float2 bb = *(const float2*)&b2[col];
            #pragma unroll
            for (int h = 0; h < 2; h++) {
                int row = r0 + warpM * 32 + mt * 16 + g + h * 8;
                float2 o = make_float2(acc3[mt][nt][h * 2] + bb.x,
                                       acc3[mt][nt][h * 2 + 1] + bb.y);
                *(float2*)&outf[(size_t)row * HD + col] = o;
            }
        }
}

// ---------------------------------------------------------------------------
extern "C" void kernel_launch(void* const* d_in, const int* in_sizes, int n_in,
                              void* d_out, int out_size) {
    const float* hs     = (const float*)d_in[0];
    const float* Wq     = (const float*)d_in[1];
    const float* coeffs = (const float*)d_in[2];
    const float* W1     = (const float*)d_in[3];
    const float* b1     = (const float*)d_in[4];
    const float* W2     = (const float*)d_in[5];
    const float* b2     = (const float*)d_in[6];
    float* out = (float*)d_out;

    prep_b1eff<<<1, MEMH>>>(W1, b1, coeffs);
    split_hs<<<(TOKENS * HIDDEN / 4) / 256, 256>>>(hs);
    cvt_wqt<<<(HIDDEN * HIDDEN) / 256, 256>>>(Wq);
    cvt_w1t<<<(MEMH * KP) / 256, 256>>>(W1);
    cvt_w2t<<<(HD * MEMH) / 256, 256>>>(W2);

    constexpr int SM1 = (2 * 128 * 20 + 128 * 20) * 4 * 2;       // 61440 B
    constexpr int SMF = SMEM_FUSED_U32 * 4;                      // 183296 B
    cudaFuncSetAttribute(gemm1_kernel, cudaFuncAttributeMaxDynamicSharedMemorySize, SM1);
    cudaFuncSetAttribute(mlp_fused,    cudaFuncAttributeMaxDynamicSharedMemorySize, SMF);

    gemm1_kernel<<<dim3(TOKENS / 128, HIDDEN / 128), 256, SM1>>>();
    mlp_fused<<<FLATR / 128, 256, SMF>>>(coeffs, b2, out);
}

// round 7
// speedup vs baseline: 2.7050x; 1.4127x over previous
#include <cuda_runtime.h>
#include <cuda_bf16.h>
#include <cuda_fp16.h>

// ---------------------------------------------------------------------------
// AtlasAttention, legacy mma.sync fp16, fused MLP.
//   GEMM1: q = clip(hs@Wq), A-side split-2 (error feeds x^3, needs guard)
//   GEMM2: h = relu(P@W1eff + b1eff), single-pass fp16 (linear error ~1.4e-4)
//   GEMM3: out = H@W2[:, :64] + b2,   single-pass fp16
//   Exact folds: b1eff (const poly block), W2[:, :64] slice.
// ---------------------------------------------------------------------------

typedef unsigned int u32;

#define TOKENS 8192
#define HIDDEN 768
#define FLATR  98304
#define MEMH   512
#define KP     192
#define HD     64

__device__ __align__(16) __half g_hs_f[TOKENS * HIDDEN];
__device__ __align__(16) __half g_hs_r[TOKENS * HIDDEN];
__device__ __align__(16) __half g_wqt[HIDDEN * HIDDEN];   // [n][k] fp16
__device__ __align__(16) __half g_w1t[MEMH * KP];         // [n=512][k=192]
__device__ __align__(16) __half g_w2t[HD * MEMH];         // [n=64][k=512]
__device__ float g_qs[(size_t)FLATR * HD];                // clipped q
__device__ float g_b1eff[MEMH];

// ---------------- helpers ----------------
__device__ __forceinline__ u32 smem_u32(const void* p) {
    u32 a; asm("{ .reg .u64 t; cvta.to.shared.u64 t, %1; cvt.u32.u64 %0, t; }"
               : "=r"(a) : "l"(p)); return a;
}
__device__ __forceinline__ u32 pack_h(__half a, __half b) {
    return (u32)__half_as_ushort(a) | ((u32)__half_as_ushort(b) << 16);
}
__device__ __forceinline__ void split2h(float v0, float v1, u32 &f, u32 &r) {
    __half h0 = __float2half_rn(v0), h1 = __float2half_rn(v1);
    __half r0 = __float2half_rn(v0 - __half2float(h0));
    __half r1 = __float2half_rn(v1 - __half2float(h1));
    f = pack_h(h0, h1); r = pack_h(r0, r1);
}
__device__ __forceinline__ void mma16816(float* c, const u32* a, const u32* b) {
    asm volatile(
        "mma.sync.aligned.m16n8k16.row.col.f32.f16.f16.f32 "
        "{%0,%1,%2,%3}, {%4,%5,%6,%7}, {%8,%9}, {%0,%1,%2,%3};"
        : "+f"(c[0]), "+f"(c[1]), "+f"(c[2]), "+f"(c[3])
        : "r"(a[0]), "r"(a[1]), "r"(a[2]), "r"(a[3]), "r"(b[0]), "r"(b[1]));
}
__device__ __forceinline__ void cpasync16(u32 dst, const void* src) {
    asm volatile("cp.async.cg.shared.global [%0], [%1], 16;" :: "r"(dst), "l"(src));
}

// ---------------- prep kernels ----------------
__global__ void prep_b1eff(const float* __restrict__ W1, const float* __restrict__ b1,
                           const float* __restrict__ coeffs) {
    int n = threadIdx.x;
    float s = 0.f;
    #pragma unroll 8
    for (int j = 0; j < HD; j++) s += W1[j * MEMH + n];
    g_b1eff[n] = b1[n] + coeffs[0] * s;
}
__global__ void split_hs(const float* __restrict__ hs) {
    int i4 = blockIdx.x * 256 + threadIdx.x;
    float4 v = ((const float4*)hs)[i4];
    u32 f0, r0, f1, r1;
    split2h(v.x, v.y, f0, r0);
    split2h(v.z, v.w, f1, r1);
    ((u32*)g_hs_f)[i4 * 2] = f0; ((u32*)g_hs_f)[i4 * 2 + 1] = f1;
    ((u32*)g_hs_r)[i4 * 2] = r0; ((u32*)g_hs_r)[i4 * 2 + 1] = r1;
}
__global__ void cvt_wqt(const float* __restrict__ Wq) {
    int idx = blockIdx.x * 256 + threadIdx.x;
    int n = idx / HIDDEN, k = idx - n * HIDDEN;
    g_wqt[idx] = __float2half_rn(Wq[(size_t)k * HIDDEN + n]);
}
__global__ void cvt_w1t(const float* __restrict__ W1) {
    int idx = blockIdx.x * 256 + threadIdx.x;
    int n = idx / KP, k = idx - n * KP;
    g_w1t[idx] = __float2half_rn(W1[(size_t)(HD + k) * MEMH + n]);
}
__global__ void cvt_w2t(const float* __restrict__ W2) {
    int idx = blockIdx.x * 256 + threadIdx.x;
    int n = idx >> 9, k = idx & 511;
    g_w2t[idx] = __float2half_rn(W2[(size_t)k * 256 + n]);
}

// ---------------- GEMM1: q = clip(hs@Wq), fp16 split-2 ----------------------
__global__ __launch_bounds__(256) void gemm1_kernel() {
    constexpr int BM = 128, BN = 128, BK = 32, NT = 8;
    constexpr int SA = 20;
    constexpr int TILE_A = BM * SA, TILE_B = BN * SA;
    constexpr int STAGE = 2 * TILE_A + TILE_B;
    constexpr int K = HIDDEN, NIT = K / BK;

    extern __shared__ u32 smem[];
    const u32 sbase = smem_u32(smem);
    const int tid = threadIdx.x, wid = tid >> 5, lane = tid & 31;
    const int g = lane >> 2, tg = lane & 3;
    const int m0 = blockIdx.x * BM, n0 = blockIdx.y * BN;
    const int warpM = wid & 3, warpN = wid >> 2;

    float acc[2][NT][4];
    #pragma unroll
    for (int mt = 0; mt < 2; mt++)
        #pragma unroll
        for (int nt = 0; nt < NT; nt++)
            #pragma unroll
            for (int j = 0; j < 4; j++) acc[mt][nt][j] = 0.f;

    auto load_stage = [&](int s, int k0) {
        const u32 stb = sbase + (u32)s * STAGE * 4;
        #pragma unroll
        for (int t = 0; t < 2; t++) {
            const __half* src = t ? g_hs_r : g_hs_f;
            #pragma unroll
            for (int idx = 0; idx < 2; idx++) {
                int l = tid + idx * 256;
                int r = l >> 2, c = l & 3;
                cpasync16(stb + (u32)(t * TILE_A + r * SA) * 4 + c * 16,
                          src + (size_t)(m0 + r) * K + k0 + c * 8);
            }
        }
        #pragma unroll
        for (int idx = 0; idx < 2; idx++) {
            int l = tid + idx * 256;
            int r = l >> 2, c = l & 3;
            cpasync16(stb + (u32)(2 * TILE_A + r * SA) * 4 + c * 16,
                      g_wqt + (size_t)(n0 + r) * K + k0 + c * 8);
        }
        asm volatile("cp.async.commit_group;");
    };

    load_stage(0, 0);
    for (int it = 0; it < NIT; it++) {
        if (it + 1 < NIT) {
            load_stage((it + 1) & 1, (it + 1) * BK);
            asm volatile("cp.async.wait_group %0;" :: "n"(1));
        } else {
            asm volatile("cp.async.wait_group %0;" :: "n"(0));
        }
        __syncthreads();
        const u32* S = smem + (it & 1) * STAGE;
        #pragma unroll
        for (int kt = 0; kt < 2; kt++) {
            u32 af[2][4], ar[2][4];
            #pragma unroll
            for (int mt = 0; mt < 2; mt++) {
                int off = (warpM * 32 + mt * 16 + g) * SA + kt * 8 + tg;
                af[mt][0] = S[off];       af[mt][1] = S[off + 8 * SA];
                af[mt][2] = S[off + 4];   af[mt][3] = S[off + 8 * SA + 4];
                const u32* SR = S + TILE_A;
                ar[mt][0] = SR[off];      ar[mt][1] = SR[off + 8 * SA];
                ar[mt][2] = SR[off + 4];  ar[mt][3] = SR[off + 8 * SA + 4];
            }
            u32 bv[NT][2];
            #pragma unroll
            for (int nt = 0; nt < NT; nt++) {
                int off = (warpN * NT * 8 + nt * 8 + g) * SA + kt * 8 + tg;
                const u32* SB = S + 2 * TILE_A;
                bv[nt][0] = SB[off]; bv[nt][1] = SB[off + 4];
            }
            #pragma unroll
            for (int mt = 0; mt < 2; mt++)
                #pragma unroll
                for (int nt = 0; nt < NT; nt++) mma16816(acc[mt][nt], af[mt], bv[nt]);
            #pragma unroll
            for (int mt = 0; mt < 2; mt++)
                #pragma unroll
                for (int nt = 0; nt < NT; nt++) mma16816(acc[mt][nt], ar[mt], bv[nt]);
        }
        __syncthreads();
    }

    #pragma unroll
    for (int mt = 0; mt < 2; mt++)
        #pragma unroll
        for (int nt = 0; nt < NT; nt++)
            #pragma unroll
            for (int h = 0; h < 2; h++) {
                int row = m0 + warpM * 32 + mt * 16 + g + h * 8;
                int col = n0 + warpN * NT * 8 + nt * 8 + tg * 2;
                float v0 = fminf(fmaxf(acc[mt][nt][h * 2],     -10.f), 10.f);
                float v1 = fminf(fmaxf(acc[mt][nt][h * 2 + 1], -10.f), 10.f);
                *(float2*)&g_qs[(size_t)row * HIDDEN + col] = make_float2(v0, v1);
            }
}

// ---------------- fused MLP kernel (single-pass fp16 GEMM2/GEMM3) -----------
#define SP 100
#define SH 36
#define O_PF   0                           // 128*100 = 12800
#define O_B2   12800                       // 64*100  = 6400
#define O_HF   19200                       // 128*36  = 4608
#define O_B3   23808                       // 2 parities x 2304
#define SMEM_FUSED_U32 28416               // * 4 = 113664 B

__global__ __launch_bounds__(256) void mlp_fused(const float* __restrict__ coeffs,
                                                 const float* __restrict__ b2,
                                                 float* __restrict__ outf) {
    extern __shared__ u32 smem[];
    const u32 sbase = smem_u32(smem);
    const int tid = threadIdx.x, wid = tid >> 5, lane = tid & 31;
    const int g = lane >> 2, tg = lane & 3;
    const int r0 = blockIdx.x * 128;
    const int warpM = wid & 3, warpN = wid >> 2;   // warpN in {0,1}

    auto load_b2 = [&](int c) {
        u32 base = sbase + O_B2 * 4;
        #pragma unroll
        for (int i = 0; i < 6; i++) {
            int l = tid + i * 256;                 // 64 rows * 24 chunks
            int n = l / 24, ch = l - n * 24;
            cpasync16(base + (u32)n * (SP * 4) + ch * 16,
                      g_w1t + (size_t)(c * 64 + n) * KP + ch * 8);
        }
    };
    auto load_b3 = [&](int c, int par) {
        u32 base = sbase + (u32)(O_B3 + par * 2304) * 4;
        #pragma unroll
        for (int i = 0; i < 2; i++) {
            int l = tid + i * 256;                 // 64 rows * 8 chunks
            int n = l >> 3, ch = l & 7;
            cpasync16(base + (u32)n * (SH * 4) + ch * 16,
                      g_w2t + (size_t)n * MEMH + c * 64 + ch * 8);
        }
    };

    load_b2(0);
    load_b3(0, 0);
    asm volatile("cp.async.commit_group;");

    // ---- poly expansion: q -> P fp16 in smem
    {
        const float c1 = coeffs[1], c2 = coeffs[2], c3 = coeffs[3];
        const float2* qb = (const float2*)(g_qs + (size_t)r0 * HD);
        #pragma unroll
        for (int i = 0; i < 16; i++) {
            int l = tid + i * 256;                 // 128 rows * 32 pairs
            int r = l >> 5, d2 = l & 31;
            float2 x = qb[l];
            float xa2 = x.x * x.x, xb2 = x.y * x.y;
            float pa[3] = {c1 * x.x, c2 * xa2, c3 * xa2 * x.x};
            float pb[3] = {c1 * x.y, c2 * xb2, c3 * xb2 * x.y};
            #pragma unroll
            for (int fi = 0; fi < 3; fi++) {
                float a = fminf(fmaxf(pa[fi], -1e6f), 1e6f);
                float b = fminf(fmaxf(pb[fi], -1e6f), 1e6f);
                smem[O_PF + r * SP + fi * 32 + d2] =
                    pack_h(__float2half_rn(a), __float2half_rn(b));
            }
        }
    }
    asm volatile("cp.async.wait_group %0;" :: "n"(0));
    __syncthreads();

    float acc3[2][4][4];
    #pragma unroll
    for (int mt = 0; mt < 2; mt++)
        #pragma unroll
        for (int nt = 0; nt < 4; nt++)
            #pragma unroll
            for (int j = 0; j < 4; j++) acc3[mt][nt][j] = 0.f;

    for (int c = 0; c < 8; c++) {
        // ---- GEMM2: [128 x 64] = P[128 x 192] * B2^T, single-pass fp16
        float acc2[2][4][4];
        #pragma unroll
        for (int mt = 0; mt < 2; mt++)
            #pragma unroll
            for (int nt = 0; nt < 4; nt++)
                #pragma unroll
                for (int j = 0; j < 4; j++) acc2[mt][nt][j] = 0.f;

        #pragma unroll
        for (int kt = 0; kt < 12; kt++) {
            u32 af[2][4];
            #pragma unroll
            for (int mt = 0; mt < 2; mt++) {
                int off = (warpM * 32 + mt * 16 + g) * SP + kt * 8 + tg;
                af[mt][0] = smem[O_PF + off];        af[mt][1] = smem[O_PF + off + 8 * SP];
                af[mt][2] = smem[O_PF + off + 4];    af[mt][3] = smem[O_PF + off + 8 * SP + 4];
            }
            u32 bv[4][2];
            #pragma unroll
            for (int nt = 0; nt < 4; nt++) {
                int off = (warpN * 32 + nt * 8 + g) * SP + kt * 8 + tg;
                bv[nt][0] = smem[O_B2 + off]; bv[nt][1] = smem[O_B2 + off + 4];
            }
            #pragma unroll
            for (int mt = 0; mt < 2; mt++)
                #pragma unroll
                for (int nt = 0; nt < 4; nt++) mma16816(acc2[mt][nt], af[mt], bv[nt]);
        }
        __syncthreads();                     // B2 consumed; H(c-1) consumed earlier

        // ---- relu -> H fp16 smem
        #pragma unroll
        for (int mt = 0; mt < 2; mt++)
            #pragma unroll
            for (int nt = 0; nt < 4; nt++) {
                int colg = c * 64 + warpN * 32 + nt * 8 + tg * 2;
                float2 bb = *(const float2*)&g_b1eff[colg];
                #pragma unroll
                for (int h = 0; h < 2; h++) {
                    int row = warpM * 32 + mt * 16 + g + h * 8;
                    int cu  = warpN * 16 + nt * 4 + tg;
                    float v0 = fmaxf(acc2[mt][nt][h * 2]     + bb.x, 0.f);
                    float v1 = fmaxf(acc2[mt][nt][h * 2 + 1] + bb.y, 0.f);
                    smem[O_HF + row * SH + cu] =
                        pack_h(__float2half_rn(v0), __float2half_rn(v1));
                }
            }
        if (c < 7) {
            load_b2(c + 1);
            load_b3(c + 1, (c + 1) & 1);
            asm volatile("cp.async.commit_group;");
        }
        __syncthreads();                     // H visible

        // ---- GEMM3 accumulate: acc3 += H[128 x 64] * B3^T (overlaps cp.async)
        const int b3o = O_B3 + (c & 1) * 2304;
        #pragma unroll
        for (int kt = 0; kt < 4; kt++) {
            u32 af[2][4];
            #pragma unroll
            for (int mt = 0; mt < 2; mt++) {
                int off = (warpM * 32 + mt * 16 + g) * SH + kt * 8 + tg;
                af[mt][0] = smem[O_HF + off];        af[mt][1] = smem[O_HF + off + 8 * SH];
                af[mt][2] = smem[O_HF + off + 4];    af[mt][3] = smem[O_HF + off + 8 * SH + 4];
            }
            u32 bv[4][2];
            #pragma unroll
            for (int nt = 0; nt < 4; nt++) {
                int off = (warpN * 32 + nt * 8 + g) * SH + kt * 8 + tg;
                bv[nt][0] = smem[b3o + off]; bv[nt][1] = smem[b3o + off + 4];
            }
            #pragma unroll
            for (int mt = 0; mt < 2; mt++)
                #pragma unroll
                for (int nt = 0; nt < 4; nt++) mma16816(acc3[mt][nt], af[mt], bv[nt]);
        }
        if (c < 7) {
            asm volatile("cp.async.wait_group %0;" :: "n"(0));
            __syncthreads();                 // next B2/B3 ready; GEMM3 done before H overwrite
        }
    }

    // ---- output: + b2
    #pragma unroll
    for (int mt = 0; mt < 2; mt++)
        #pragma unroll
        for (int nt = 0; nt < 4; nt++) {
            int col = warpN * 32 + nt * 8 + tg * 2;
            float2 bb = *(const float2*)&b2[col];
            #pragma unroll
            for (int h = 0; h < 2; h++) {
                int row = r0 + warpM * 32 + mt * 16 + g + h * 8;
                float2 o = make_float2(acc3[mt][nt][h * 2] + bb.x,
                                       acc3[mt][nt][h * 2 + 1] + bb.y);
                *(float2*)&outf[(size_t)row * HD + col] = o;
            }
        }
}

// ---------------------------------------------------------------------------
extern "C" void kernel_launch(void* const* d_in, const int* in_sizes, int n_in,
                              void* d_out, int out_size) {
    const float* hs     = (const float*)d_in[0];
    const float* Wq     = (const float*)d_in[1];
    const float* coeffs = (const float*)d_in[2];
    const float* W1     = (const float*)d_in[3];
    const float* b1     = (const float*)d_in[4];
    const float* W2     = (const float*)d_in[5];
    const float* b2     = (const float*)d_in[6];
    float* out = (float*)d_out;

    prep_b1eff<<<1, MEMH>>>(W1, b1, coeffs);
    split_hs<<<(TOKENS * HIDDEN / 4) / 256, 256>>>(hs);
    cvt_wqt<<<(HIDDEN * HIDDEN) / 256, 256>>>(Wq);
    cvt_w1t<<<(MEMH * KP) / 256, 256>>>(W1);
    cvt_w2t<<<(HD * MEMH) / 256, 256>>>(W2);

    constexpr int SM1 = (2 * 128 * 20 + 128 * 20) * 4 * 2;       // 61440 B
    constexpr int SMF = SMEM_FUSED_U32 * 4;                      // 113664 B
    cudaFuncSetAttribute(gemm1_kernel, cudaFuncAttributeMaxDynamicSharedMemorySize, SM1);
    cudaFuncSetAttribute(mlp_fused,    cudaFuncAttributeMaxDynamicSharedMemorySize, SMF);

    gemm1_kernel<<<dim3(TOKENS / 128, HIDDEN / 128), 256, SM1>>>();
    mlp_fused<<<FLATR / 128, 256, SMF>>>(coeffs, b2, out);
}

// round 9
// speedup vs baseline: 3.4192x; 1.2640x over previous
#include <cuda_runtime.h>
#include <cuda_bf16.h>
#include <cuda_fp16.h>

// ---------------------------------------------------------------------------
// AtlasAttention, legacy mma.sync fp16 single-pass everywhere, fused MLP.
//   GEMM1: q = clip(hs@Wq)                  (fp16 x fp16, fp32 accum)
//   GEMM2: h = relu(P@W1eff + b1eff)        (fp16 single-pass)
//   GEMM3: out = H@W2[:, :64] + b2          (fp16 single-pass)
//   Exact folds: b1eff (const poly block), W2[:, :64] slice.
//   All prep fused into one branch-ladder kernel (kills launch latency).
// ---------------------------------------------------------------------------

typedef unsigned int u32;

#define TOKENS 8192
#define HIDDEN 768
#define FLATR  98304
#define MEMH   512
#define KP     192
#define HD     64

__device__ __align__(16) __half g_hs_f[TOKENS * HIDDEN];
__device__ __align__(16) __half g_wqt[HIDDEN * HIDDEN];   // [n][k] fp16
__device__ __align__(16) __half g_w1t[MEMH * KP];         // [n=512][k=192]
__device__ __align__(16) __half g_w2t[HD * MEMH];         // [n=64][k=512]
__device__ float g_qs[(size_t)FLATR * HD];                // clipped q
__device__ float g_b1eff[MEMH];

// ---------------- helpers ----------------
__device__ __forceinline__ u32 smem_u32(const void* p) {
    u32 a; asm("{ .reg .u64 t; cvta.to.shared.u64 t, %1; cvt.u32.u64 %0, t; }"
               : "=r"(a) : "l"(p)); return a;
}
__device__ __forceinline__ u32 pack_h(__half a, __half b) {
    return (u32)__half_as_ushort(a) | ((u32)__half_as_ushort(b) << 16);
}
__device__ __forceinline__ void mma16816(float* c, const u32* a, const u32* b) {
    asm volatile(
        "mma.sync.aligned.m16n8k16.row.col.f32.f16.f16.f32 "
        "{%0,%1,%2,%3}, {%4,%5,%6,%7}, {%8,%9}, {%0,%1,%2,%3};"
        : "+f"(c[0]), "+f"(c[1]), "+f"(c[2]), "+f"(c[3])
        : "r"(a[0]), "r"(a[1]), "r"(a[2]), "r"(a[3]), "r"(b[0]), "r"(b[1]));
}
__device__ __forceinline__ void cpasync16(u32 dst, const void* src) {
    asm volatile("cp.async.cg.shared.global [%0], [%1], 16;" :: "r"(dst), "l"(src));
}

// ---------------- fused prep kernel ----------------
// blocks [0,6144): hs -> fp16  | [6144,8448): Wq^T | [8448,8832): W1eff^T
// [8832,8960): W2^T slice      | [8960,8962): b1eff fold
#define NB_HS  6144
#define NB_WQT 2304
#define NB_W1T 384
#define NB_W2T 128
#define NB_ALL (NB_HS + NB_WQT + NB_W1T + NB_W2T + 2)

__global__ void prep_all(const float* __restrict__ hs, const float* __restrict__ Wq,
                         const float* __restrict__ W1, const float* __restrict__ W2,
                         const float* __restrict__ b1, const float* __restrict__ coeffs) {
    const int b = blockIdx.x, tid = threadIdx.x;
    if (b < NB_HS) {
        int i4 = b * 256 + tid;
        float4 v = ((const float4*)hs)[i4];
        ((u32*)g_hs_f)[i4 * 2]     = pack_h(__float2half_rn(v.x), __float2half_rn(v.y));
        ((u32*)g_hs_f)[i4 * 2 + 1] = pack_h(__float2half_rn(v.z), __float2half_rn(v.w));
    } else if (b < NB_HS + NB_WQT) {
        int idx = (b - NB_HS) * 256 + tid;
        int n = idx / HIDDEN, k = idx - n * HIDDEN;
        g_wqt[idx] = __float2half_rn(Wq[(size_t)k * HIDDEN + n]);
    } else if (b < NB_HS + NB_WQT + NB_W1T) {
        int idx = (b - NB_HS - NB_WQT) * 256 + tid;
        int n = idx / KP, k = idx - n * KP;
        g_w1t[idx] = __float2half_rn(W1[(size_t)(HD + k) * MEMH + n]);
    } else if (b < NB_HS + NB_WQT + NB_W1T + NB_W2T) {
        int idx = (b - NB_HS - NB_WQT - NB_W1T) * 256 + tid;
        int n = idx >> 9, k = idx & 511;
        g_w2t[idx] = __float2half_rn(W2[(size_t)k * 256 + n]);
    } else {
        int n = (b - NB_HS - NB_WQT - NB_W1T - NB_W2T) * 256 + tid;
        float s = 0.f;
        #pragma unroll 8
        for (int j = 0; j < HD; j++) s += W1[j * MEMH + n];
        g_b1eff[n] = b1[n] + coeffs[0] * s;
    }
}

// ---------------- GEMM1: q = clip(hs@Wq), single-pass fp16 ------------------
__global__ __launch_bounds__(256) void gemm1_kernel() {
    constexpr int BM = 128, BN = 128, BK = 32, NT = 8;
    constexpr int SA = 20;
    constexpr int TILE_A = BM * SA, TILE_B = BN * SA;
    constexpr int STAGE = TILE_A + TILE_B;
    constexpr int K = HIDDEN, NIT = K / BK;

    extern __shared__ u32 smem[];
    const u32 sbase = smem_u32(smem);
    const int tid = threadIdx.x, wid = tid >> 5, lane = tid & 31;
    const int g = lane >> 2, tg = lane & 3;
    const int m0 = blockIdx.x * BM, n0 = blockIdx.y * BN;
    const int warpM = wid & 3, warpN = wid >> 2;

    float acc[2][NT][4];
    #pragma unroll
    for (int mt = 0; mt < 2; mt++)
        #pragma unroll
        for (int nt = 0; nt < NT; nt++)
            #pragma unroll
            for (int j = 0; j < 4; j++) acc[mt][nt][j] = 0.f;

    auto load_stage = [&](int s, int k0) {
        const u32 stb = sbase + (u32)s * STAGE * 4;
        #pragma unroll
        for (int idx = 0; idx < 2; idx++) {
            int l = tid + idx * 256;
            int r = l >> 2, c = l & 3;
            cpasync16(stb + (u32)(r * SA) * 4 + c * 16,
                      g_hs_f + (size_t)(m0 + r) * K + k0 + c * 8);
        }
        #pragma unroll
        for (int idx = 0; idx < 2; idx++) {
            int l = tid + idx * 256;
            int r = l >> 2, c = l & 3;
            cpasync16(stb + (u32)(TILE_A + r * SA) * 4 + c * 16,
                      g_wqt + (size_t)(n0 + r) * K + k0 + c * 8);
        }
        asm volatile("cp.async.commit_group;");
    };

    load_stage(0, 0);
    for (int it = 0; it < NIT; it++) {
        if (it + 1 < NIT) {
            load_stage((it + 1) & 1, (it + 1) * BK);
            asm volatile("cp.async.wait_group %0;" :: "n"(1));
        } else {
            asm volatile("cp.async.wait_group %0;" :: "n"(0));
        }
        __syncthreads();
        const u32* S = smem + (it & 1) * STAGE;
        #pragma unroll
        for (int kt = 0; kt < 2; kt++) {
            u32 af[2][4];
            #pragma unroll
            for (int mt = 0; mt < 2; mt++) {
                int off = (warpM * 32 + mt * 16 + g) * SA + kt * 8 + tg;
                af[mt][0] = S[off];       af[mt][1] = S[off + 8 * SA];
                af[mt][2] = S[off + 4];   af[mt][3] = S[off + 8 * SA + 4];
            }
            u32 bv[NT][2];
            #pragma unroll
            for (int nt = 0; nt < NT; nt++) {
                int off = (warpN * NT * 8 + nt * 8 + g) * SA + kt * 8 + tg;
                const u32* SB = S + TILE_A;
                bv[nt][0] = SB[off]; bv[nt][1] = SB[off + 4];
            }
            #pragma unroll
            for (int mt = 0; mt < 2; mt++)
                #pragma unroll
                for (int nt = 0; nt < NT; nt++) mma16816(acc[mt][nt], af[mt], bv[nt]);
        }
        __syncthreads();
    }

    #pragma unroll
    for (int mt = 0; mt < 2; mt++)
        #pragma unroll
        for (int nt = 0; nt < NT; nt++)
            #pragma unroll
            for (int h = 0; h < 2; h++) {
                int row = m0 + warpM * 32 + mt * 16 + g + h * 8;
                int col = n0 + warpN * NT * 8 + nt * 8 + tg * 2;
                float v0 = fminf(fmaxf(acc[mt][nt][h * 2],     -10.f), 10.f);
                float v1 = fminf(fmaxf(acc[mt][nt][h * 2 + 1], -10.f), 10.f);
                *(float2*)&g_qs[(size_t)row * HIDDEN + col] = make_float2(v0, v1);
            }
}

// ---------------- fused MLP kernel (single-pass fp16 GEMM2/GEMM3) -----------
#define SP 100
#define SH 36
#define O_PF   0                           // 128*100 = 12800
#define O_B2   12800                       // 64*100  = 6400
#define O_HF   19200                       // 128*36  = 4608
#define O_B3   23808                       // 2 parities x 2304
#define SMEM_FUSED_U32 28416               // * 4 = 113664 B

__global__ __launch_bounds__(256) void mlp_fused(const float* __restrict__ coeffs,
                                                 const float* __restrict__ b2,
                                                 float* __restrict__ outf) {
    extern __shared__ u32 smem[];
    const u32 sbase = smem_u32(smem);
    const int tid = threadIdx.x, wid = tid >> 5, lane = tid & 31;
    const int g = lane >> 2, tg = lane & 3;
    const int r0 = blockIdx.x * 128;
    const int warpM = wid & 3, warpN = wid >> 2;   // warpN in {0,1}

    auto load_b2 = [&](int c) {
        u32 base = sbase + O_B2 * 4;
        #pragma unroll
        for (int i = 0; i < 6; i++) {
            int l = tid + i * 256;                 // 64 rows * 24 chunks
            int n = l / 24, ch = l - n * 24;
            cpasync16(base + (u32)n * (SP * 4) + ch * 16,
                      g_w1t + (size_t)(c * 64 + n) * KP + ch * 8);
        }
    };
    auto load_b3 = [&](int c, int par) {
        u32 base = sbase + (u32)(O_B3 + par * 2304) * 4;
        #pragma unroll
        for (int i = 0; i < 2; i++) {
            int l = tid + i * 256;                 // 64 rows * 8 chunks
            int n = l >> 3, ch = l & 7;
            cpasync16(base + (u32)n * (SH * 4) + ch * 16,
                      g_w2t + (size_t)n * MEMH + c * 64 + ch * 8);
        }
    };

    load_b2(0);
    load_b3(0, 0);
    asm volatile("cp.async.commit_group;");

    // ---- poly expansion: q -> P fp16 in smem
    {
        const float c1 = coeffs[1], c2 = coeffs[2], c3 = coeffs[3];
        const float2* qb = (const float2*)(g_qs + (size_t)r0 * HD);
        #pragma unroll
        for (int i = 0; i < 16; i++) {
            int l = tid + i * 256;                 // 128 rows * 32 pairs
            int r = l >> 5, d2 = l & 31;
            float2 x = qb[l];
            float xa2 = x.x * x.x, xb2 = x.y * x.y;
            float pa[3] = {c1 * x.x, c2 * xa2, c3 * xa2 * x.x};
            float pb[3] = {c1 * x.y, c2 * xb2, c3 * xb2 * x.y};
            #pragma unroll
            for (int fi = 0; fi < 3; fi++) {
                float a = fminf(fmaxf(pa[fi], -1e6f), 1e6f);
                float b = fminf(fmaxf(pb[fi], -1e6f), 1e6f);
                smem[O_PF + r * SP + fi * 32 + d2] =
                    pack_h(__float2half_rn(a), __float2half_rn(b));
            }
        }
    }
    asm volatile("cp.async.wait_group %0;" :: "n"(0));
    __syncthreads();

    float acc3[2][4][4];
    #pragma unroll
    for (int mt = 0; mt < 2; mt++)
        #pragma unroll
        for (int nt = 0; nt < 4; nt++)
            #pragma unroll
            for (int j = 0; j < 4; j++) acc3[mt][nt][j] = 0.f;

    for (int c = 0; c < 8; c++) {
        // ---- GEMM2: [128 x 64] = P[128 x 192] * B2^T, single-pass fp16
        float acc2[2][4][4];
        #pragma unroll
        for (int mt = 0; mt < 2; mt++)
            #pragma unroll
            for (int nt = 0; nt < 4; nt++)
                #pragma unroll
                for (int j = 0; j < 4; j++) acc2[mt][nt][j] = 0.f;

        #pragma unroll
        for (int kt = 0; kt < 12; kt++) {
            u32 af[2][4];
            #pragma unroll
            for (int mt = 0; mt < 2; mt++) {
                int off = (warpM * 32 + mt * 16 + g) * SP + kt * 8 + tg;
                af[mt][0] = smem[O_PF + off];        af[mt][1] = smem[O_PF + off + 8 * SP];
                af[mt][2] = smem[O_PF + off + 4];    af[mt][3] = smem[O_PF + off + 8 * SP + 4];
            }
            u32 bv[4][2];
            #pragma unroll
            for (int nt = 0; nt < 4; nt++) {
                int off = (warpN * 32 + nt * 8 + g) * SP + kt * 8 + tg;
                bv[nt][0] = smem[O_B2 + off]; bv[nt][1] = smem[O_B2 + off + 4];
            }
            #pragma unroll
            for (int mt = 0; mt < 2; mt++)
                #pragma unroll
                for (int nt = 0; nt < 4; nt++) mma16816(acc2[mt][nt], af[mt], bv[nt]);
        }
        __syncthreads();                     // B2 consumed; H(c-1) consumed earlier

        // ---- relu -> H fp16 smem
        #pragma unroll
        for (int mt = 0; mt < 2; mt++)
            #pragma unroll
            for (int nt = 0; nt < 4; nt++) {
                int colg = c * 64 + warpN * 32 + nt * 8 + tg * 2;
                float2 bb = *(const float2*)&g_b1eff[colg];
                #pragma unroll
                for (int h = 0; h < 2; h++) {
                    int row = warpM * 32 + mt * 16 + g + h * 8;
                    int cu  = warpN * 16 + nt * 4 + tg;
                    float v0 = fmaxf(acc2[mt][nt][h * 2]     + bb.x, 0.f);
                    float v1 = fmaxf(acc2[mt][nt][h * 2 + 1] + bb.y, 0.f);
                    smem[O_HF + row * SH + cu] =
                        pack_h(__float2half_rn(v0), __float2half_rn(v1));
                }
            }
        if (c < 7) {
            load_b2(c + 1);
            load_b3(c + 1, (c + 1) & 1);
            asm volatile("cp.async.commit_group;");
        }
        __syncthreads();                     // H visible

        // ---- GEMM3 accumulate: acc3 += H[128 x 64] * B3^T (overlaps cp.async)
        const int b3o = O_B3 + (c & 1) * 2304;
        #pragma unroll
        for (int kt = 0; kt < 4; kt++) {
            u32 af[2][4];
            #pragma unroll
            for (int mt = 0; mt < 2; mt++) {
                int off = (warpM * 32 + mt * 16 + g) * SH + kt * 8 + tg;
                af[mt][0] = smem[O_HF + off];        af[mt][1] = smem[O_HF + off + 8 * SH];
                af[mt][2] = smem[O_HF + off + 4];    af[mt][3] = smem[O_HF + off + 8 * SH + 4];
            }
            u32 bv[4][2];
            #pragma unroll
            for (int nt = 0; nt < 4; nt++) {
                int off = (warpN * 32 + nt * 8 + g) * SH + kt * 8 + tg;
                bv[nt][0] = smem[b3o + off]; bv[nt][1] = smem[b3o + off + 4];
            }
            #pragma unroll
            for (int mt = 0; mt < 2; mt++)
                #pragma unroll
                for (int nt = 0; nt < 4; nt++) mma16816(acc3[mt][nt], af[mt], bv[nt]);
        }
        if (c < 7) {
            asm volatile("cp.async.wait_group %0;" :: "n"(0));
            __syncthreads();                 // next B2/B3 ready; GEMM3 done before H overwrite
        }
    }

    // ---- output: + b2
    #pragma unroll
    for (int mt = 0; mt < 2; mt++)
        #pragma unroll
        for (int nt = 0; nt < 4; nt++) {
            int col = warpN * 32 + nt * 8 + tg * 2;
            float2 bb = *(const float2*)&b2[col];
            #pragma unroll
            for (int h = 0; h < 2; h++) {
                int row = r0 + warpM * 32 + mt * 16 + g + h * 8;
                float2 o = make_float2(acc3[mt][nt][h * 2] + bb.x,
                                       acc3[mt][nt][h * 2 + 1] + bb.y);
                *(float2*)&outf[(size_t)row * HD + col] = o;
            }
        }
}

// ---------------------------------------------------------------------------
extern "C" void kernel_launch(void* const* d_in, const int* in_sizes, int n_in,
                              void* d_out, int out_size) {
    const float* hs     = (const float*)d_in[0];
    const float* Wq     = (const float*)d_in[1];
    const float* coeffs = (const float*)d_in[2];
    const float* W1     = (const float*)d_in[3];
    const float* b1     = (const float*)d_in[4];
    const float* W2     = (const float*)d_in[5];
    const float* b2     = (const float*)d_in[6];
    float* out = (float*)d_out;

    prep_all<<<NB_ALL, 256>>>(hs, Wq, W1, W2, b1, coeffs);

    constexpr int SM1 = (128 * 20 + 128 * 20) * 4 * 2;           // 40960 B
    constexpr int SMF = SMEM_FUSED_U32 * 4;                      // 113664 B
    cudaFuncSetAttribute(gemm1_kernel, cudaFuncAttributeMaxDynamicSharedMemorySize, SM1);
    cudaFuncSetAttribute(mlp_fused,    cudaFuncAttributeMaxDynamicSharedMemorySize, SMF);

    gemm1_kernel<<<dim3(TOKENS / 128, HIDDEN / 128), 256, SM1>>>();
    mlp_fused<<<FLATR / 128, 256, SMF>>>(coeffs, b2, out);
}

// round 11
// speedup vs baseline: 3.5540x; 1.0394x over previous
#include <cuda_runtime.h>
#include <cuda_bf16.h>
#include <cuda_fp16.h>

// ---------------------------------------------------------------------------
// AtlasAttention, legacy mma.sync fp16 single-pass, fused MLP.
//   GEMM1: q = clip(hs@Wq) -> g_qs (fp16)
//   GEMM2: h = relu(P@W1eff + b1eff)   GEMM3: out = H@W2[:, :64] + b2
//   Exact folds: b1eff (const poly block), W2[:, :64] slice.
//   Prep fused into one kernel; Wq transpose via coalesced smem tiles.
// ---------------------------------------------------------------------------

typedef unsigned int u32;

#define TOKENS 8192
#define HIDDEN 768
#define FLATR  98304
#define MEMH   512
#define KP     192
#define HD     64

__device__ __align__(16) __half g_hs_f[TOKENS * HIDDEN];
__device__ __align__(16) __half g_wqt[HIDDEN * HIDDEN];   // [n][k] fp16
__device__ __align__(16) __half g_w1t[MEMH * KP];         // [n=512][k=192]
__device__ __align__(16) __half g_w2t[HD * MEMH];         // [n=64][k=512]
__device__ __align__(16) __half g_qs[(size_t)TOKENS * HIDDEN];  // clipped q, fp16
__device__ float g_b1eff[MEMH];

// ---------------- helpers ----------------
__device__ __forceinline__ u32 smem_u32(const void* p) {
    u32 a; asm("{ .reg .u64 t; cvta.to.shared.u64 t, %1; cvt.u32.u64 %0, t; }"
               : "=r"(a) : "l"(p)); return a;
}
__device__ __forceinline__ u32 pack_h(__half a, __half b) {
    return (u32)__half_as_ushort(a) | ((u32)__half_as_ushort(b) << 16);
}
__device__ __forceinline__ void mma16816(float* c, const u32* a, const u32* b) {
    asm volatile(
        "mma.sync.aligned.m16n8k16.row.col.f32.f16.f16.f32 "
        "{%0,%1,%2,%3}, {%4,%5,%6,%7}, {%8,%9}, {%0,%1,%2,%3};"
        : "+f"(c[0]), "+f"(c[1]), "+f"(c[2]), "+f"(c[3])
        : "r"(a[0]), "r"(a[1]), "r"(a[2]), "r"(a[3]), "r"(b[0]), "r"(b[1]));
}
__device__ __forceinline__ void cpasync16(u32 dst, const void* src) {
    asm volatile("cp.async.cg.shared.global [%0], [%1], 16;" :: "r"(dst), "l"(src));
}

// ---------------- fused prep kernel ----------------
// [0,6144):          hs -> fp16 (coalesced)
// [6144,6720):       Wq^T via 32x32 smem tile transpose (24x24 tiles)
// [6720,7104):       W1eff^T
// [7104,7232):       W2^T slice
// [7232,7234):       b1eff fold
#define NB_HS   6144
#define NB_WQT  576
#define NB_W1T  384
#define NB_W2T  128
#define NB_ALL  (NB_HS + NB_WQT + NB_W1T + NB_W2T + 2)

__global__ void prep_all(const float* __restrict__ hs, const float* __restrict__ Wq,
                         const float* __restrict__ W1, const float* __restrict__ W2,
                         const float* __restrict__ b1, const float* __restrict__ coeffs) {
    const int b = blockIdx.x, tid = threadIdx.x;
    if (b < NB_HS) {
        int i4 = b * 256 + tid;
        float4 v = ((const float4*)hs)[i4];
        ((u32*)g_hs_f)[i4 * 2]     = pack_h(__float2half_rn(v.x), __float2half_rn(v.y));
        ((u32*)g_hs_f)[i4 * 2 + 1] = pack_h(__float2half_rn(v.z), __float2half_rn(v.w));
    } else if (b < NB_HS + NB_WQT) {
        // 32x32 tile transpose, both sides coalesced
        __shared__ float ts[32][33];
        int t = b - NB_HS;
        int kb = (t / 24) * 32, nb = (t % 24) * 32;
        int tx = tid & 31, ty = tid >> 5;            // ty in [0,8)
        #pragma unroll
        for (int i = 0; i < 4; i++) {
            int row = ty + i * 8;
            ts[row][tx] = Wq[(size_t)(kb + row) * HIDDEN + nb + tx];
        }
        __syncthreads();
        #pragma unroll
        for (int i = 0; i < 4; i++) {
            int n = ty + i * 8;                       // local n
            g_wqt[(size_t)(nb + n) * HIDDEN + kb + tx] = __float2half_rn(ts[tx][n]);
        }
    } else if (b < NB_HS + NB_WQT + NB_W1T) {
        int idx = (b - NB_HS - NB_WQT) * 256 + tid;
        int n = idx / KP, k = idx - n * KP;
        g_w1t[idx] = __float2half_rn(W1[(size_t)(HD + k) * MEMH + n]);
    } else if (b < NB_HS + NB_WQT + NB_W1T + NB_W2T) {
        int idx = (b - NB_HS - NB_WQT - NB_W1T) * 256 + tid;
        int n = idx >> 9, k = idx & 511;
        g_w2t[idx] = __float2half_rn(W2[(size_t)k * 256 + n]);
    } else {
        int n = (b - NB_HS - NB_WQT - NB_W1T - NB_W2T) * 256 + tid;
        float s = 0.f;
        #pragma unroll 8
        for (int j = 0; j < HD; j++) s += W1[j * MEMH + n];
        g_b1eff[n] = b1[n] + coeffs[0] * s;
    }
}

// ---------------- GEMM1: q = clip(hs@Wq), single-pass fp16 ------------------
__global__ __launch_bounds__(256) void gemm1_kernel() {
    constexpr int BM = 128, BN = 128, BK = 32, NT = 8;
    constexpr int SA = 20;
    constexpr int TILE_A = BM * SA, TILE_B = BN * SA;
    constexpr int STAGE = TILE_A + TILE_B;
    constexpr int K = HIDDEN, NIT = K / BK;

    extern __shared__ u32 smem[];
    const u32 sbase = smem_u32(smem);
    const int tid = threadIdx.x, wid = tid >> 5, lane = tid & 31;
    const int g = lane >> 2, tg = lane & 3;
    const int m0 = blockIdx.x * BM, n0 = blockIdx.y * BN;
    const int warpM = wid & 3, warpN = wid >> 2;

    float acc[2][NT][4];
    #pragma unroll
    for (int mt = 0; mt < 2; mt++)
        #pragma unroll
        for (int nt = 0; nt < NT; nt++)
            #pragma unroll
            for (int j = 0; j < 4; j++) acc[mt][nt][j] = 0.f;

    auto load_stage = [&](int s, int k0) {
        const u32 stb = sbase + (u32)s * STAGE * 4;
        #pragma unroll
        for (int idx = 0; idx < 2; idx++) {
            int l = tid + idx * 256;
            int r = l >> 2, c = l & 3;
            cpasync16(stb + (u32)(r * SA) * 4 + c * 16,
                      g_hs_f + (size_t)(m0 + r) * K + k0 + c * 8);
        }
        #pragma unroll
        for (int idx = 0; idx < 2; idx++) {
            int l = tid + idx * 256;
            int r = l >> 2, c = l & 3;
            cpasync16(stb + (u32)(TILE_A + r * SA) * 4 + c * 16,
                      g_wqt + (size_t)(n0 + r) * K + k0 + c * 8);
        }
        asm volatile("cp.async.commit_group;");
    };

    load_stage(0, 0);
    for (int it = 0; it < NIT; it++) {
        if (it + 1 < NIT) {
            load_stage((it + 1) & 1, (it + 1) * BK);
            asm volatile("cp.async.wait_group %0;" :: "n"(1));
        } else {
            asm volatile("cp.async.wait_group %0;" :: "n"(0));
        }
        __syncthreads();
        const u32* S = smem + (it & 1) * STAGE;
        #pragma unroll
        for (int kt = 0; kt < 2; kt++) {
            u32 af[2][4];
            #pragma unroll
            for (int mt = 0; mt < 2; mt++) {
                int off = (warpM * 32 + mt * 16 + g) * SA + kt * 8 + tg;
                af[mt][0] = S[off];       af[mt][1] = S[off + 8 * SA];
                af[mt][2] = S[off + 4];   af[mt][3] = S[off + 8 * SA + 4];
            }
            u32 bv[NT][2];
            #pragma unroll
            for (int nt = 0; nt < NT; nt++) {
                int off = (warpN * NT * 8 + nt * 8 + g) * SA + kt * 8 + tg;
                const u32* SB = S + TILE_A;
                bv[nt][0] = SB[off]; bv[nt][1] = SB[off + 4];
            }
            #pragma unroll
            for (int mt = 0; mt < 2; mt++)
                #pragma unroll
                for (int nt = 0; nt < NT; nt++) mma16816(acc[mt][nt], af[mt], bv[nt]);
        }
        __syncthreads();
    }

    #pragma unroll
    for (int mt = 0; mt < 2; mt++)
        #pragma unroll
        for (int nt = 0; nt < NT; nt++)
            #pragma unroll
            for (int h = 0; h < 2; h++) {
                int row = m0 + warpM * 32 + mt * 16 + g + h * 8;
                int col = n0 + warpN * NT * 8 + nt * 8 + tg * 2;
                float v0 = fminf(fmaxf(acc[mt][nt][h * 2],     -10.f), 10.f);
                float v1 = fminf(fmaxf(acc[mt][nt][h * 2 + 1], -10.f), 10.f);
                ((u32*)g_qs)[((size_t)row * HIDDEN + col) >> 1] =
                    pack_h(__float2half_rn(v0), __float2half_rn(v1));
            }
}

// ---------------- fused MLP kernel (single-pass fp16 GEMM2/GEMM3) -----------
#define SP 100
#define SH 36
#define O_PF   0                           // 128*100 = 12800
#define O_B2   12800                       // 64*100  = 6400
#define O_HF   19200                       // 128*36  = 4608
#define O_B3   23808                       // 2 parities x 2304
#define SMEM_FUSED_U32 28416               // * 4 = 113664 B

__global__ __launch_bounds__(256) void mlp_fused(const float* __restrict__ coeffs,
                                                 const float* __restrict__ b2,
                                                 float* __restrict__ outf) {
    extern __shared__ u32 smem[];
    const u32 sbase = smem_u32(smem);
    const int tid = threadIdx.x, wid = tid >> 5, lane = tid & 31;
    const int g = lane >> 2, tg = lane & 3;
    const int r0 = blockIdx.x * 128;
    const int warpM = wid & 3, warpN = wid >> 2;   // warpN in {0,1}

    auto load_b2 = [&](int c) {
        u32 base = sbase + O_B2 * 4;
        #pragma unroll
        for (int i = 0; i < 6; i++) {
            int l = tid + i * 256;                 // 64 rows * 24 chunks
            int n = l / 24, ch = l - n * 24;
            cpasync16(base + (u32)n * (SP * 4) + ch * 16,
                      g_w1t + (size_t)(c * 64 + n) * KP + ch * 8);
        }
    };
    auto load_b3 = [&](int c, int par) {
        u32 base = sbase + (u32)(O_B3 + par * 2304) * 4;
        #pragma unroll
        for (int i = 0; i < 2; i++) {
            int l = tid + i * 256;                 // 64 rows * 8 chunks
            int n = l >> 3, ch = l & 7;
            cpasync16(base + (u32)n * (SH * 4) + ch * 16,
                      g_w2t + (size_t)n * MEMH + c * 64 + ch * 8);
        }
    };

    load_b2(0);
    load_b3(0, 0);
    asm volatile("cp.async.commit_group;");

    // ---- poly expansion: q (fp16 pairs) -> P fp16 in smem
    {
        const float c1 = coeffs[1], c2 = coeffs[2], c3 = coeffs[3];
        const u32* qb = (const u32*)g_qs + (size_t)r0 * (HD / 2);
        #pragma unroll
        for (int i = 0; i < 16; i++) {
            int l = tid + i * 256;                 // 128 rows * 32 pairs
            int r = l >> 5, d2 = l & 31;
            u32 pv = qb[l];
            __half2 h2 = *(__half2*)&pv;
            float xa = __low2float(h2), xb = __high2float(h2);
            float xa2 = xa * xa, xb2 = xb * xb;
            float pa[3] = {c1 * xa, c2 * xa2, c3 * xa2 * xa};
            float pb[3] = {c1 * xb, c2 * xb2, c3 * xb2 * xb};
            #pragma unroll
            for (int fi = 0; fi < 3; fi++) {
                float a = fminf(fmaxf(pa[fi], -1e6f), 1e6f);
                float b = fminf(fmaxf(pb[fi], -1e6f), 1e6f);
                smem[O_PF + r * SP + fi * 32 + d2] =
                    pack_h(__float2half_rn(a), __float2half_rn(b));
            }
        }
    }
    asm volatile("cp.async.wait_group %0;" :: "n"(0));
    __syncthreads();

    float acc3[2][4][4];
    #pragma unroll
    for (int mt = 0; mt < 2; mt++)
        #pragma unroll
        for (int nt = 0; nt < 4; nt++)
            #pragma unroll
            for (int j = 0; j < 4; j++) acc3[mt][nt][j] = 0.f;

    for (int c = 0; c < 8; c++) {
        // ---- GEMM2: [128 x 64] = P[128 x 192] * B2^T, single-pass fp16
        float acc2[2][4][4];
        #pragma unroll
        for (int mt = 0; mt < 2; mt++)
            #pragma unroll
            for (int nt = 0; nt < 4; nt++)
                #pragma unroll
                for (int j = 0; j < 4; j++) acc2[mt][nt][j] = 0.f;

        #pragma unroll
        for (int kt = 0; kt < 12; kt++) {
            u32 af[2][4];
            #pragma unroll
            for (int mt = 0; mt < 2; mt++) {
                int off = (warpM * 32 + mt * 16 + g) * SP + kt * 8 + tg;
                af[mt][0] = smem[O_PF + off];        af[mt][1] = smem[O_PF + off + 8 * SP];
                af[mt][2] = smem[O_PF + off + 4];    af[mt][3] = smem[O_PF + off + 8 * SP + 4];
            }
            u32 bv[4][2];
            #pragma unroll
            for (int nt = 0; nt < 4; nt++) {
                int off = (warpN * 32 + nt * 8 + g) * SP + kt * 8 + tg;
                bv[nt][0] = smem[O_B2 + off]; bv[nt][1] = smem[O_B2 + off + 4];
            }
            #pragma unroll
            for (int mt = 0; mt < 2; mt++)
                #pragma unroll
                for (int nt = 0; nt < 4; nt++) mma16816(acc2[mt][nt], af[mt], bv[nt]);
        }
        __syncthreads();                     // B2 consumed; H(c-1) consumed earlier

        // ---- relu -> H fp16 smem
        #pragma unroll
        for (int mt = 0; mt < 2; mt++)
            #pragma unroll
            for (int nt = 0; nt < 4; nt++) {
                int colg = c * 64 + warpN * 32 + nt * 8 + tg * 2;
                float2 bb = *(const float2*)&g_b1eff[colg];
                #pragma unroll
                for (int h = 0; h < 2; h++) {
                    int row = warpM * 32 + mt * 16 + g + h * 8;
                    int cu  = warpN * 16 + nt * 4 + tg;
                    float v0 = fmaxf(acc2[mt][nt][h * 2]     + bb.x, 0.f);
                    float v1 = fmaxf(acc2[mt][nt][h * 2 + 1] + bb.y, 0.f);
                    smem[O_HF + row * SH + cu] =
                        pack_h(__float2half_rn(v0), __float2half_rn(v1));
                }
            }
        if (c < 7) {
            load_b2(c + 1);
            load_b3(c + 1, (c + 1) & 1);
            asm volatile("cp.async.commit_group;");
        }
        __syncthreads();                     // H visible

        // ---- GEMM3 accumulate: acc3 += H[128 x 64] * B3^T (overlaps cp.async)
        const int b3o = O_B3 + (c & 1) * 2304;
        #pragma unroll
        for (int kt = 0; kt < 4; kt++) {
            u32 af[2][4];
            #pragma unroll
            for (int mt = 0; mt < 2; mt++) {
                int off = (warpM * 32 + mt * 16 + g) * SH + kt * 8 + tg;
                af[mt][0] = smem[O_HF + off];        af[mt][1] = smem[O_HF + off + 8 * SH];
                af[mt][2] = smem[O_HF + off + 4];    af[mt][3] = smem[O_HF + off + 8 * SH + 4];
            }
            u32 bv[4][2];
            #pragma unroll
            for (int nt = 0; nt < 4; nt++) {
                int off = (warpN * 32 + nt * 8 + g) * SH + kt * 8 + tg;
                bv[nt][0] = smem[b3o + off]; bv[nt][1] = smem[b3o + off + 4];
            }
            #pragma unroll
            for (int mt = 0; mt < 2; mt++)
                #pragma unroll
                for (int nt = 0; nt < 4; nt++) mma16816(acc3[mt][nt], af[mt], bv[nt]);
        }
        if (c < 7) {
            asm volatile("cp.async.wait_group %0;" :: "n"(0));
            __syncthreads();                 // next B2/B3 ready; GEMM3 done before H overwrite
        }
    }

    // ---- output: + b2
    #pragma unroll
    for (int mt = 0; mt < 2; mt++)
        #pragma unroll
        for (int nt = 0; nt < 4; nt++) {
            int col = warpN * 32 + nt * 8 + tg * 2;
            float2 bb = *(const float2*)&b2[col];
            #pragma unroll
            for (int h = 0; h < 2; h++) {
                int row = r0 + warpM * 32 + mt * 16 + g + h * 8;
                float2 o = make_float2(acc3[mt][nt][h * 2] + bb.x,
                                       acc3[mt][nt][h * 2 + 1] + bb.y);
                *(float2*)&outf[(size_t)row * HD + col] = o;
            }
        }
}

// ---------------------------------------------------------------------------
extern "C" void kernel_launch(void* const* d_in, const int* in_sizes, int n_in,
                              void* d_out, int out_size) {
    const float* hs     = (const float*)d_in[0];
    const float* Wq     = (const float*)d_in[1];
    const float* coeffs = (const float*)d_in[2];
    const float* W1     = (const float*)d_in[3];
    const float* b1     = (const float*)d_in[4];
    const float* W2     = (const float*)d_in[5];
    const float* b2     = (const float*)d_in[6];
    float* out = (float*)d_out;

    prep_all<<<NB_ALL, 256>>>(hs, Wq, W1, W2, b1, coeffs);

    constexpr int SM1 = (128 * 20 + 128 * 20) * 4 * 2;           // 40960 B
    constexpr int SMF = SMEM_FUSED_U32 * 4;                      // 113664 B
    cudaFuncSetAttribute(gemm1_kernel, cudaFuncAttributeMaxDynamicSharedMemorySize, SM1);
    cudaFuncSetAttribute(mlp_fused,    cudaFuncAttributeMaxDynamicSharedMemorySize, SMF);

    gemm1_kernel<<<dim3(TOKENS / 128, HIDDEN / 128), 256, SM1>>>();
    mlp_fused<<<FLATR / 128, 256, SMF>>>(coeffs, b2, out);
}

// round 12
// speedup vs baseline: 3.5983x; 1.0125x over previous
#include <cuda_runtime.h>
#include <cuda_bf16.h>
#include <cuda_fp16.h>

// ---------------------------------------------------------------------------
// AtlasAttention, legacy mma.sync fp16 single-pass, fused MLP.
//   GEMM1: q = clip(hs@Wq) -> g_qs (fp16)
//   GEMM2: h = relu(P@W1eff + b1eff)   GEMM3: out = H@W2[:, :64] + b2
//   Exact folds: b1eff (const poly block), W2[:, :64] slice.
//   mlp_fused: 2 CTAs/SM (syncthreads/epilogue bubbles hidden by co-resident CTA)
//   prep: hs convert with 4x per-thread ILP + packed 8B stores.
// ---------------------------------------------------------------------------

typedef unsigned int u32;

#define TOKENS 8192
#define HIDDEN 768
#define FLATR  98304
#define MEMH   512
#define KP     192
#define HD     64

__device__ __align__(16) __half g_hs_f[TOKENS * HIDDEN];
__device__ __align__(16) __half g_wqt[HIDDEN * HIDDEN];   // [n][k] fp16
__device__ __align__(16) __half g_w1t[MEMH * KP];         // [n=512][k=192]
__device__ __align__(16) __half g_w2t[HD * MEMH];         // [n=64][k=512]
__device__ __align__(16) __half g_qs[(size_t)TOKENS * HIDDEN];  // clipped q, fp16
__device__ float g_b1eff[MEMH];

// ---------------- helpers ----------------
__device__ __forceinline__ u32 smem_u32(const void* p) {
    u32 a; asm("{ .reg .u64 t; cvta.to.shared.u64 t, %1; cvt.u32.u64 %0, t; }"
               : "=r"(a) : "l"(p)); return a;
}
__device__ __forceinline__ u32 pack_h(__half a, __half b) {
    return (u32)__half_as_ushort(a) | ((u32)__half_as_ushort(b) << 16);
}
__device__ __forceinline__ void mma16816(float* c, const u32* a, const u32* b) {
    asm volatile(
        "mma.sync.aligned.m16n8k16.row.col.f32.f16.f16.f32 "
        "{%0,%1,%2,%3}, {%4,%5,%6,%7}, {%8,%9}, {%0,%1,%2,%3};"
        : "+f"(c[0]), "+f"(c[1]), "+f"(c[2]), "+f"(c[3])
        : "r"(a[0]), "r"(a[1]), "r"(a[2]), "r"(a[3]), "r"(b[0]), "r"(b[1]));
}
__device__ __forceinline__ void cpasync16(u32 dst, const void* src) {
    asm volatile("cp.async.cg.shared.global [%0], [%1], 16;" :: "r"(dst), "l"(src));
}

// ---------------- fused prep kernel ----------------
// [0,1536):       hs -> fp16 (4 float4s per thread, packed uint2 stores)
// [1536,2112):    Wq^T via 32x32 smem tile transpose (24x24 tiles)
// [2112,2496):    W1eff^T
// [2496,2624):    W2^T slice
// [2624,2626):    b1eff fold
#define NB_HS   1536
#define NB_WQT  576
#define NB_W1T  384
#define NB_W2T  128
#define NB_ALL  (NB_HS + NB_WQT + NB_W1T + NB_W2T + 2)

__global__ void prep_all(const float* __restrict__ hs, const float* __restrict__ Wq,
                         const float* __restrict__ W1, const float* __restrict__ W2,
                         const float* __restrict__ b1, const float* __restrict__ coeffs) {
    const int b = blockIdx.x, tid = threadIdx.x;
    if (b < NB_HS) {
        #pragma unroll
        for (int j = 0; j < 4; j++) {
            int i4 = (b * 256 + tid) + j * (NB_HS * 256);
            float4 v = ((const float4*)hs)[i4];
            u32 f0 = pack_h(__float2half_rn(v.x), __float2half_rn(v.y));
            u32 f1 = pack_h(__float2half_rn(v.z), __float2half_rn(v.w));
            ((uint2*)g_hs_f)[i4] = make_uint2(f0, f1);
        }
    } else if (b < NB_HS + NB_WQT) {
        // 32x32 tile transpose, both sides coalesced
        __shared__ float ts[32][33];
        int t = b - NB_HS;
        int kb = (t / 24) * 32, nb = (t % 24) * 32;
        int tx = tid & 31, ty = tid >> 5;            // ty in [0,8)
        #pragma unroll
        for (int i = 0; i < 4; i++) {
            int row = ty + i * 8;
            ts[row][tx] = Wq[(size_t)(kb + row) * HIDDEN + nb + tx];
        }
        __syncthreads();
        #pragma unroll
        for (int i = 0; i < 4; i++) {
            int n = ty + i * 8;                       // local n
            g_wqt[(size_t)(nb + n) * HIDDEN + kb + tx] = __float2half_rn(ts[tx][n]);
        }
    } else if (b < NB_HS + NB_WQT + NB_W1T) {
        int idx = (b - NB_HS - NB_WQT) * 256 + tid;
        int n = idx / KP, k = idx - n * KP;
        g_w1t[idx] = __float2half_rn(W1[(size_t)(HD + k) * MEMH + n]);
    } else if (b < NB_HS + NB_WQT + NB_W1T + NB_W2T) {
        int idx = (b - NB_HS - NB_WQT - NB_W1T) * 256 + tid;
        int n = idx >> 9, k = idx & 511;
        g_w2t[idx] = __float2half_rn(W2[(size_t)k * 256 + n]);
    } else {
        int n = (b - NB_HS - NB_WQT - NB_W1T - NB_W2T) * 256 + tid;
        float s = 0.f;
        #pragma unroll 8
        for (int j = 0; j < HD; j++) s += W1[j * MEMH + n];
        g_b1eff[n] = b1[n] + coeffs[0] * s;
    }
}

// ---------------- GEMM1: q = clip(hs@Wq), single-pass fp16 ------------------
__global__ __launch_bounds__(256) void gemm1_kernel() {
    constexpr int BM = 128, BN = 128, BK = 32, NT = 8;
    constexpr int SA = 20;
    constexpr int TILE_A = BM * SA, TILE_B = BN * SA;
    constexpr int STAGE = TILE_A + TILE_B;
    constexpr int K = HIDDEN, NIT = K / BK;

    extern __shared__ u32 smem[];
    const u32 sbase = smem_u32(smem);
    const int tid = threadIdx.x, wid = tid >> 5, lane = tid & 31;
    const int g = lane >> 2, tg = lane & 3;
    const int m0 = blockIdx.x * BM, n0 = blockIdx.y * BN;
    const int warpM = wid & 3, warpN = wid >> 2;

    float acc[2][NT][4];
    #pragma unroll
    for (int mt = 0; mt < 2; mt++)
        #pragma unroll
        for (int nt = 0; nt < NT; nt++)
            #pragma unroll
            for (int j = 0; j < 4; j++) acc[mt][nt][j] = 0.f;

    auto load_stage = [&](int s, int k0) {
        const u32 stb = sbase + (u32)s * STAGE * 4;
        #pragma unroll
        for (int idx = 0; idx < 2; idx++) {
            int l = tid + idx * 256;
            int r = l >> 2, c = l & 3;
            cpasync16(stb + (u32)(r * SA) * 4 + c * 16,
                      g_hs_f + (size_t)(m0 + r) * K + k0 + c * 8);
        }
        #pragma unroll
        for (int idx = 0; idx < 2; idx++) {
            int l = tid + idx * 256;
            int r = l >> 2, c = l & 3;
            cpasync16(stb + (u32)(TILE_A + r * SA) * 4 + c * 16,
                      g_wqt + (size_t)(n0 + r) * K + k0 + c * 8);
        }
        asm volatile("cp.async.commit_group;");
    };

    load_stage(0, 0);
    for (int it = 0; it < NIT; it++) {
        if (it + 1 < NIT) {
            load_stage((it + 1) & 1, (it + 1) * BK);
            asm volatile("cp.async.wait_group %0;" :: "n"(1));
        } else {
            asm volatile("cp.async.wait_group %0;" :: "n"(0));
        }
        __syncthreads();
        const u32* S = smem + (it & 1) * STAGE;
        #pragma unroll
        for (int kt = 0; kt < 2; kt++) {
            u32 af[2][4];
            #pragma unroll
            for (int mt = 0; mt < 2; mt++) {
                int off = (warpM * 32 + mt * 16 + g) * SA + kt * 8 + tg;
                af[mt][0] = S[off];       af[mt][1] = S[off + 8 * SA];
                af[mt][2] = S[off + 4];   af[mt][3] = S[off + 8 * SA + 4];
            }
            u32 bv[NT][2];
            #pragma unroll
            for (int nt = 0; nt < NT; nt++) {
                int off = (warpN * NT * 8 + nt * 8 + g) * SA + kt * 8 + tg;
                const u32* SB = S + TILE_A;
                bv[nt][0] = SB[off]; bv[nt][1] = SB[off + 4];
            }
            #pragma unroll
            for (int mt = 0; mt < 2; mt++)
                #pragma unroll
                for (int nt = 0; nt < NT; nt++) mma16816(acc[mt][nt], af[mt], bv[nt]);
        }
        __syncthreads();
    }

    #pragma unroll
    for (int mt = 0; mt < 2; mt++)
        #pragma unroll
        for (int nt = 0; nt < NT; nt++)
            #pragma unroll
            for (int h = 0; h < 2; h++) {
                int row = m0 + warpM * 32 + mt * 16 + g + h * 8;
                int col = n0 + warpN * NT * 8 + nt * 8 + tg * 2;
                float v0 = fminf(fmaxf(acc[mt][nt][h * 2],     -10.f), 10.f);
                float v1 = fminf(fmaxf(acc[mt][nt][h * 2 + 1], -10.f), 10.f);
                ((u32*)g_qs)[((size_t)row * HIDDEN + col) >> 1] =
                    pack_h(__float2half_rn(v0), __float2half_rn(v1));
            }
}

// ---------------- fused MLP kernel (single-pass fp16 GEMM2/GEMM3) -----------
#define SP 100
#define SH 36
#define O_PF   0                           // 128*100 = 12800
#define O_B2   12800                       // 64*100  = 6400
#define O_HF   19200                       // 128*36  = 4608
#define O_B3   23808                       // 2 parities x 2304
#define SMEM_FUSED_U32 28416               // * 4 = 113664 B; x2 CTAs = 227328 <= 228KB

__global__ __launch_bounds__(256, 2) void mlp_fused(const float* __restrict__ coeffs,
                                                    const float* __restrict__ b2,
                                                    float* __restrict__ outf) {
    extern __shared__ u32 smem[];
    const u32 sbase = smem_u32(smem);
    const int tid = threadIdx.x, wid = tid >> 5, lane = tid & 31;
    const int g = lane >> 2, tg = lane & 3;
    const int r0 = blockIdx.x * 128;
    const int warpM = wid & 3, warpN = wid >> 2;   // warpN in {0,1}

    auto load_b2 = [&](int c) {
        u32 base = sbase + O_B2 * 4;
        #pragma unroll
        for (int i = 0; i < 6; i++) {
            int l = tid + i * 256;                 // 64 rows * 24 chunks
            int n = l / 24, ch = l - n * 24;
            cpasync16(base + (u32)n * (SP * 4) + ch * 16,
                      g_w1t + (size_t)(c * 64 + n) * KP + ch * 8);
        }
    };
    auto load_b3 = [&](int c, int par) {
        u32 base = sbase + (u32)(O_B3 + par * 2304) * 4;
        #pragma unroll
        for (int i = 0; i < 2; i++) {
            int l = tid + i * 256;                 // 64 rows * 8 chunks
            int n = l >> 3, ch = l & 7;
            cpasync16(base + (u32)n * (SH * 4) + ch * 16,
                      g_w2t + (size_t)n * MEMH + c * 64 + ch * 8);
        }
    };

    load_b2(0);
    load_b3(0, 0);
    asm volatile("cp.async.commit_group;");

    // ---- poly expansion: q (fp16 pairs) -> P fp16 in smem
    {
        const float c1 = coeffs[1], c2 = coeffs[2], c3 = coeffs[3];
        const u32* qb = (const u32*)g_qs + (size_t)r0 * (HD / 2);
        #pragma unroll
        for (int i = 0; i < 16; i++) {
            int l = tid + i * 256;                 // 128 rows * 32 pairs
            int r = l >> 5, d2 = l & 31;
            u32 pv = qb[l];
            __half2 h2 = *(__half2*)&pv;
            float xa = __low2float(h2), xb = __high2float(h2);
            float xa2 = xa * xa, xb2 = xb * xb;
            float pa[3] = {c1 * xa, c2 * xa2, c3 * xa2 * xa};
            float pb[3] = {c1 * xb, c2 * xb2, c3 * xb2 * xb};
            #pragma unroll
            for (int fi = 0; fi < 3; fi++) {
                float a = fminf(fmaxf(pa[fi], -1e6f), 1e6f);
                float b = fminf(fmaxf(pb[fi], -1e6f), 1e6f);
                smem[O_PF + r * SP + fi * 32 + d2] =
                    pack_h(__float2half_rn(a), __float2half_rn(b));
            }
        }
    }
    asm volatile("cp.async.wait_group %0;" :: "n"(0));
    __syncthreads();

    float acc3[2][4][4];
    #pragma unroll
    for (int mt = 0; mt < 2; mt++)
        #pragma unroll
        for (int nt = 0; nt < 4; nt++)
            #pragma unroll
            for (int j = 0; j < 4; j++) acc3[mt][nt][j] = 0.f;

    for (int c = 0; c < 8; c++) {
        // ---- GEMM2: [128 x 64] = P[128 x 192] * B2^T, single-pass fp16
        float acc2[2][4][4];
        #pragma unroll
        for (int mt = 0; mt < 2; mt++)
            #pragma unroll
            for (int nt = 0; nt < 4; nt++)
                #pragma unroll
                for (int j = 0; j < 4; j++) acc2[mt][nt][j] = 0.f;

        #pragma unroll
        for (int kt = 0; kt < 12; kt++) {
            u32 af[2][4];
            #pragma unroll
            for (int mt = 0; mt < 2; mt++) {
                int off = (warpM * 32 + mt * 16 + g) * SP + kt * 8 + tg;
                af[mt][0] = smem[O_PF + off];        af[mt][1] = smem[O_PF + off + 8 * SP];
                af[mt][2] = smem[O_PF + off + 4];    af[mt][3] = smem[O_PF + off + 8 * SP + 4];
            }
            u32 bv[4][2];
            #pragma unroll
            for (int nt = 0; nt < 4; nt++) {
                int off = (warpN * 32 + nt * 8 + g) * SP + kt * 8 + tg;
                bv[nt][0] = smem[O_B2 + off]; bv[nt][1] = smem[O_B2 + off + 4];
            }
            #pragma unroll
            for (int mt = 0; mt < 2; mt++)
                #pragma unroll
                for (int nt = 0; nt < 4; nt++) mma16816(acc2[mt][nt], af[mt], bv[nt]);
        }
        __syncthreads();                     // B2 consumed; H(c-1) consumed earlier

        // ---- relu -> H fp16 smem
        #pragma unroll
        for (int mt = 0; mt < 2; mt++)
            #pragma unroll
            for (int nt = 0; nt < 4; nt++) {
                int colg = c * 64 + warpN * 32 + nt * 8 + tg * 2;
                float2 bb = *(const float2*)&g_b1eff[colg];
                #pragma unroll
                for (int h = 0; h < 2; h++) {
                    int row = warpM * 32 + mt * 16 + g + h * 8;
                    int cu  = warpN * 16 + nt * 4 + tg;
                    float v0 = fmaxf(acc2[mt][nt][h * 2]     + bb.x, 0.f);
                    float v1 = fmaxf(acc2[mt][nt][h * 2 + 1] + bb.y, 0.f);
                    smem[O_HF + row * SH + cu] =
                        pack_h(__float2half_rn(v0), __float2half_rn(v1));
                }
            }
        if (c < 7) {
            load_b2(c + 1);
            load_b3(c + 1, (c + 1) & 1);
            asm volatile("cp.async.commit_group;");
        }
        __syncthreads();                     // H visible

        // ---- GEMM3 accumulate: acc3 += H[128 x 64] * B3^T (overlaps cp.async)
        const int b3o = O_B3 + (c & 1) * 2304;
        #pragma unroll
        for (int kt = 0; kt < 4; kt++) {
            u32 af[2][4];
            #pragma unroll
            for (int mt = 0; mt < 2; mt++) {
                int off = (warpM * 32 + mt * 16 + g) * SH + kt * 8 + tg;
                af[mt][0] = smem[O_HF + off];        af[mt][1] = smem[O_HF + off + 8 * SH];
                af[mt][2] = smem[O_HF + off + 4];    af[mt][3] = smem[O_HF + off + 8 * SH + 4];
            }
            u32 bv[4][2];
            #pragma unroll
            for (int nt = 0; nt < 4; nt++) {
                int off = (warpN * 32 + nt * 8 + g) * SH + kt * 8 + tg;
                bv[nt][0] = smem[b3o + off]; bv[nt][1] = smem[b3o + off + 4];
            }
            #pragma unroll
            for (int mt = 0; mt < 2; mt++)
                #pragma unroll
                for (int nt = 0; nt < 4; nt++) mma16816(acc3[mt][nt], af[mt], bv[nt]);
        }
        if (c < 7) {
            asm volatile("cp.async.wait_group %0;" :: "n"(0));
            __syncthreads();                 // next B2/B3 ready; GEMM3 done before H overwrite
        }
    }

    // ---- output: + b2
    #pragma unroll
    for (int mt = 0; mt < 2; mt++)
        #pragma unroll
        for (int nt = 0; nt < 4; nt++) {
            int col = warpN * 32 + nt * 8 + tg * 2;
            float2 bb = *(const float2*)&b2[col];
            #pragma unroll
            for (int h = 0; h < 2; h++) {
                int row = r0 + warpM * 32 + mt * 16 + g + h * 8;
                float2 o = make_float2(acc3[mt][nt][h * 2] + bb.x,
                                       acc3[mt][nt][h * 2 + 1] + bb.y);
                *(float2*)&outf[(size_t)row * HD + col] = o;
            }
        }
}

// ---------------------------------------------------------------------------
extern "C" void kernel_launch(void* const* d_in, const int* in_sizes, int n_in,
                              void* d_out, int out_size) {
    const float* hs     = (const float*)d_in[0];
    const float* Wq     = (const float*)d_in[1];
    const float* coeffs = (const float*)d_in[2];
    const float* W1     = (const float*)d_in[3];
    const float* b1     = (const float*)d_in[4];
    const float* W2     = (const float*)d_in[5];
    const float* b2     = (const float*)d_in[6];
    float* out = (float*)d_out;

    prep_all<<<NB_ALL, 256>>>(hs, Wq, W1, W2, b1, coeffs);

    constexpr int SM1 = (128 * 20 + 128 * 20) * 4 * 2;           // 40960 B
    constexpr int SMF = SMEM_FUSED_U32 * 4;                      // 113664 B
    cudaFuncSetAttribute(gemm1_kernel, cudaFuncAttributeMaxDynamicSharedMemorySize, SM1);
    cudaFuncSetAttribute(mlp_fused,    cudaFuncAttributeMaxDynamicSharedMemorySize, SMF);

    gemm1_kernel<<<dim3(TOKENS / 128, HIDDEN / 128), 256, SM1>>>();
    mlp_fused<<<FLATR / 128, 256, SMF>>>(coeffs, b2, out);
}